// round 1
// baseline (speedup 1.0000x reference)
#include <cuda_runtime.h>

// Problem dims
#define BB 32
#define NN 1024
#define DD 256
#define HH 512

// Scratch (allocation-free rule: __device__ globals)
__device__ float g_q[BB * NN * HH];   // 64 MB
__device__ float g_k[BB * NN * HH];   // 64 MB
__device__ float g_v[BB * NN * HH];   // 64 MB
__device__ float g_s[(long long)BB * NN * NN]; // 128 MB
__device__ float g_o[BB * NN * HH];   // 64 MB

// ---------------------------------------------------------------------------
// Tiled GEMM:
//   C[m][n] = act( sum_k A[m][k] * B(k,n) + bias[n] )
// A is M x K row-major.
// If BT:  B is N x K row-major (C = A * B^T)     -- "NT"
// else:   B is K x N row-major (C = A * B)       -- "NN"
// Batched via blockIdx.z with element strides sA/sB/sC.
// BM=BN=128, BK=16, 256 threads, 8x8 per-thread micro-tile.
// ---------------------------------------------------------------------------
template <bool BT, bool BIAS, bool RELU>
__global__ __launch_bounds__(256) void gemm_kernel(
    const float* __restrict__ A, const float* __restrict__ Bm,
    const float* __restrict__ bias, float* __restrict__ C,
    int M, int N, int K,
    long long sA, long long sB, long long sC)
{
    const int BM = 128, BN = 128, BK = 16;
    __shared__ float As[BK][BM];
    __shared__ float Bs[BK][BN];

    const int bz = blockIdx.z;
    A  += (long long)bz * sA;
    Bm += (long long)bz * sB;
    C  += (long long)bz * sC;

    const int m0 = blockIdx.y * BM;
    const int n0 = blockIdx.x * BN;
    const int tid = threadIdx.x;
    const int ty = tid >> 4;    // 0..15
    const int tx = tid & 15;    // 0..15

    float acc[8][8];
#pragma unroll
    for (int i = 0; i < 8; i++)
#pragma unroll
        for (int j = 0; j < 8; j++) acc[i][j] = 0.0f;

    for (int k0 = 0; k0 < K; k0 += BK) {
        // ---- load A tile (BM x BK), store transposed As[k][m] ----
#pragma unroll
        for (int r = 0; r < 2; r++) {
            int idx = tid + r * 256;          // float4 index, 0..511
            int m  = idx >> 2;                // 0..127
            int k4 = (idx & 3) * 4;           // 0,4,8,12
            float4 v = *(const float4*)(A + (long long)(m0 + m) * K + k0 + k4);
            As[k4 + 0][m] = v.x;
            As[k4 + 1][m] = v.y;
            As[k4 + 2][m] = v.z;
            As[k4 + 3][m] = v.w;
        }
        // ---- load B tile ----
        if (BT) {
            // B is N x K row-major: tile rows n, cols k -> store transposed
#pragma unroll
            for (int r = 0; r < 2; r++) {
                int idx = tid + r * 256;
                int n  = idx >> 2;
                int k4 = (idx & 3) * 4;
                float4 v = *(const float4*)(Bm + (long long)(n0 + n) * K + k0 + k4);
                Bs[k4 + 0][n] = v.x;
                Bs[k4 + 1][n] = v.y;
                Bs[k4 + 2][n] = v.z;
                Bs[k4 + 3][n] = v.w;
            }
        } else {
            // B is K x N row-major: rows k contiguous in n -> direct float4
#pragma unroll
            for (int r = 0; r < 2; r++) {
                int idx = tid + r * 256;      // 512 float4 over 16x128
                int k  = idx >> 5;            // 0..15
                int n4 = (idx & 31) * 4;      // 0..124
                *(float4*)&Bs[k][n4] =
                    *(const float4*)(Bm + (long long)(k0 + k) * N + n0 + n4);
            }
        }
        __syncthreads();

        // ---- compute ----
#pragma unroll
        for (int kk = 0; kk < BK; kk++) {
            float4 a0 = *(float4*)&As[kk][ty * 8];
            float4 a1 = *(float4*)&As[kk][ty * 8 + 4];
            float4 b0 = *(float4*)&Bs[kk][tx * 8];
            float4 b1 = *(float4*)&Bs[kk][tx * 8 + 4];
            float a[8] = {a0.x, a0.y, a0.z, a0.w, a1.x, a1.y, a1.z, a1.w};
            float b[8] = {b0.x, b0.y, b0.z, b0.w, b1.x, b1.y, b1.z, b1.w};
#pragma unroll
            for (int i = 0; i < 8; i++)
#pragma unroll
                for (int j = 0; j < 8; j++)
                    acc[i][j] = fmaf(a[i], b[j], acc[i][j]);
        }
        __syncthreads();
    }

    // ---- epilogue ----
#pragma unroll
    for (int i = 0; i < 8; i++) {
        int m = m0 + ty * 8 + i;
#pragma unroll
        for (int j = 0; j < 8; j += 4) {
            int n = n0 + tx * 8 + j;
            float4 v;
            v.x = acc[i][j + 0];
            v.y = acc[i][j + 1];
            v.z = acc[i][j + 2];
            v.w = acc[i][j + 3];
            if (BIAS) {
                v.x += bias[n + 0];
                v.y += bias[n + 1];
                v.z += bias[n + 2];
                v.w += bias[n + 3];
            }
            if (RELU) {
                v.x = fmaxf(v.x, 0.0f);
                v.y = fmaxf(v.y, 0.0f);
                v.z = fmaxf(v.z, 0.0f);
                v.w = fmaxf(v.w, 0.0f);
            }
            *(float4*)(C + (long long)m * N + n) = v;
        }
    }
}

// ---------------------------------------------------------------------------
// Row softmax over 1024-wide rows of S. One block (256 threads) per row.
// ---------------------------------------------------------------------------
__global__ __launch_bounds__(256) void softmax_kernel(float* __restrict__ S)
{
    long long row = blockIdx.x;
    float* p = S + row * (long long)NN;
    int tid = threadIdx.x;

    float4 v = *(float4*)(p + tid * 4);

    __shared__ float red[8];

    // max reduce
    float m = fmaxf(fmaxf(v.x, v.y), fmaxf(v.z, v.w));
#pragma unroll
    for (int o = 16; o > 0; o >>= 1)
        m = fmaxf(m, __shfl_xor_sync(0xffffffffu, m, o));
    if ((tid & 31) == 0) red[tid >> 5] = m;
    __syncthreads();
    float bm = red[0];
#pragma unroll
    for (int i = 1; i < 8; i++) bm = fmaxf(bm, red[i]);
    __syncthreads();

    // exp + sum reduce
    v.x = __expf(v.x - bm);
    v.y = __expf(v.y - bm);
    v.z = __expf(v.z - bm);
    v.w = __expf(v.w - bm);
    float s = v.x + v.y + v.z + v.w;
#pragma unroll
    for (int o = 16; o > 0; o >>= 1)
        s += __shfl_xor_sync(0xffffffffu, s, o);
    if ((tid & 31) == 0) red[tid >> 5] = s;
    __syncthreads();
    float bs = red[0];
#pragma unroll
    for (int i = 1; i < 8; i++) bs += red[i];

    float inv = 1.0f / bs;
    v.x *= inv; v.y *= inv; v.z *= inv; v.w *= inv;
    *(float4*)(p + tid * 4) = v;
}

// ---------------------------------------------------------------------------
// kernel_launch
// Inputs (metadata order): h, Wv, bv, Wk, bk, Wq, bq, Wo, bo
// ---------------------------------------------------------------------------
extern "C" void kernel_launch(void* const* d_in, const int* in_sizes, int n_in,
                              void* d_out, int out_size)
{
    const float* h  = (const float*)d_in[0];
    const float* Wv = (const float*)d_in[1];
    const float* bv = (const float*)d_in[2];
    const float* Wk = (const float*)d_in[3];
    const float* bk = (const float*)d_in[4];
    const float* Wq = (const float*)d_in[5];
    const float* bq = (const float*)d_in[6];
    const float* Wo = (const float*)d_in[7];
    const float* bo = (const float*)d_in[8];
    float* out = (float*)d_out;

    float *q, *k, *v, *s, *o;
    cudaGetSymbolAddress((void**)&q, g_q);
    cudaGetSymbolAddress((void**)&k, g_k);
    cudaGetSymbolAddress((void**)&v, g_v);
    cudaGetSymbolAddress((void**)&s, g_s);
    cudaGetSymbolAddress((void**)&o, g_o);

    const int M = BB * NN; // 32768

    // Q/K/V projections: [32768,256] x [512,256]^T -> relu -> [32768,512]
    {
        dim3 grid(HH / 128, M / 128, 1);
        gemm_kernel<true, true, true><<<grid, 256>>>(h, Wv, bv, v, M, HH, DD, 0, 0, 0);
        gemm_kernel<true, true, true><<<grid, 256>>>(h, Wq, bq, q, M, HH, DD, 0, 0, 0);
        gemm_kernel<true, true, true><<<grid, 256>>>(h, Wk, bk, k, M, HH, DD, 0, 0, 0);
    }

    // S = Q K^T per batch: [1024,512] x [1024,512]^T -> [1024,1024]
    {
        dim3 grid(NN / 128, NN / 128, BB);
        gemm_kernel<true, false, false><<<grid, 256>>>(
            q, k, nullptr, s, NN, NN, HH,
            (long long)NN * HH, (long long)NN * HH, (long long)NN * NN);
    }

    // softmax rows
    softmax_kernel<<<BB * NN, 256>>>(s);

    // O = att V per batch: [1024,1024] x [1024,512] -> [1024,512]
    {
        dim3 grid(HH / 128, NN / 128, BB);
        gemm_kernel<false, false, false><<<grid, 256>>>(
            s, v, nullptr, o, NN, HH, NN,
            (long long)NN * NN, (long long)NN * HH, (long long)NN * HH);
    }

    // out = relu(O Wo^T + bo): [32768,512] x [256,512]^T -> [32768,256]
    {
        dim3 grid(DD / 128, M / 128, 1);
        gemm_kernel<true, true, true><<<grid, 256>>>(o, Wo, bo, out, M, DD, HH, 0, 0, 0);
    }
}

// round 4
// speedup vs baseline: 2.0372x; 2.0372x over previous
#include <cuda_runtime.h>
#include <cuda_bf16.h>
#include <cstdint>

// Problem dims
#define BB 32
#define NN 1024
#define DD 256
#define HH 512

// ---------------- bf-pair scratch (uint32 per element: lo<<16 | hi) ----------
__device__ uint32_t g_hb[BB * NN * DD];                 // packed h
__device__ uint32_t g_wq[HH * DD], g_wk[HH * DD], g_wv[HH * DD], g_wo[DD * HH];
__device__ uint32_t g_q[BB * NN * HH];
__device__ uint32_t g_k[BB * NN * HH];
__device__ uint32_t g_v[BB * NN * HH];
__device__ uint32_t g_vt[BB * HH * NN];                 // [b][h][n]
__device__ uint32_t g_s[(long long)BB * NN * NN];
__device__ uint32_t g_o[BB * NN * HH];

// ---------------- helpers ----------------
__device__ __forceinline__ uint32_t bf_pack(float x) {
    __nv_bfloat16 h = __float2bfloat16(x);                 // rn
    float hf = __bfloat162float(h);
    __nv_bfloat16 l = __float2bfloat16(x - hf);
    unsigned short hb = *reinterpret_cast<unsigned short*>(&h);
    unsigned short lb = *reinterpret_cast<unsigned short*>(&l);
    return ((uint32_t)lb << 16) | (uint32_t)hb;
}
__device__ __forceinline__ float bf_unpack(uint32_t w) {
    unsigned short hb = (unsigned short)(w & 0xffffu);
    unsigned short lb = (unsigned short)(w >> 16);
    __nv_bfloat16 h = *reinterpret_cast<__nv_bfloat16*>(&hb);
    __nv_bfloat16 l = *reinterpret_cast<__nv_bfloat16*>(&lb);
    return __bfloat162float(h) + __bfloat162float(l);
}

__device__ __forceinline__ uint32_t smem_u32(const void* p) {
    uint32_t a;
    asm("{ .reg .u64 t; cvta.to.shared.u64 t, %1; cvt.u32.u64 %0, t; }" : "=r"(a) : "l"(p));
    return a;
}
__device__ __forceinline__ void cp16(uint32_t dst, const void* src) {
    asm volatile("cp.async.cg.shared.global [%0], [%1], 16;" :: "r"(dst), "l"(src));
}
#define CP_COMMIT() asm volatile("cp.async.commit_group;" ::: "memory")
#define CP_WAIT(n)  asm volatile("cp.async.wait_group %0;" :: "n"(n) : "memory")

__device__ __forceinline__ void mma_bf16(float* d, const uint32_t* a, const uint32_t* b) {
    asm volatile(
        "mma.sync.aligned.m16n8k16.row.col.f32.bf16.bf16.f32 "
        "{%0,%1,%2,%3}, {%4,%5,%6,%7}, {%8,%9}, {%0,%1,%2,%3};"
        : "+f"(d[0]), "+f"(d[1]), "+f"(d[2]), "+f"(d[3])
        : "r"(a[0]), "r"(a[1]), "r"(a[2]), "r"(a[3]), "r"(b[0]), "r"(b[1]));
}

// ---------------- GEMM config ----------------
#define BM 128
#define BN 128
#define BK 32
#define STAGES 3
#define THREADS 256
#define LD_W 36                       // 32 elem + 4 pad (keeps 16B row alignment)
#define A_OFF 0
#define B_OFF (128 * LD_W)
#define STAGE_W (2 * 128 * LD_W)      // 9216 words
#define SMEM_BYTES (STAGES * STAGE_W * 4)   // 110592

// ---------------------------------------------------------------------------
// NT GEMM on bf-pair data: C = act(A * B^T + bias)
// A: M x K (elements = packed bf-pair), B: N x K. Batched via blockIdx.z.
// OUTBF: write bf-pair uint32; else fp32.
// ---------------------------------------------------------------------------
template <bool BIAS, bool RELU, bool OUTBF>
__global__ __launch_bounds__(THREADS) void tc_gemm(
    const uint32_t* __restrict__ A, const uint32_t* __restrict__ B,
    const float* __restrict__ bias, void* __restrict__ Cv,
    int M, int N, int K, long long sA, long long sB, long long sC)
{
    extern __shared__ uint32_t smw[];
    const uint32_t sbase = smem_u32(smw);

    const int tid = threadIdx.x;
    const int wid = tid >> 5;
    const int lane = tid & 31;
    const int g = lane >> 2;
    const int t = lane & 3;

    A += (long long)blockIdx.z * sA;
    B += (long long)blockIdx.z * sB;
    const int m0 = blockIdx.y * BM;
    const int n0 = blockIdx.x * BN;

    const int wm = (wid & 3) * 32;
    const int wn = (wid >> 2) * 64;

    float acc[2][8][4];
#pragma unroll
    for (int i = 0; i < 2; i++)
#pragma unroll
        for (int j = 0; j < 8; j++)
#pragma unroll
            for (int r = 0; r < 4; r++) acc[i][j][r] = 0.0f;

    const int niter = K / BK;

    auto issue_loads = [&](int it) {
        const int s = it % STAGES;
        const int k0 = it * BK;
        const uint32_t stg = sbase + (s * STAGE_W) * 4;
#pragma unroll
        for (int c = 0; c < 4; c++) {
            const int id = tid + c * 256;          // 0..1023
            const int row = id >> 3, cc = id & 7;  // 8 x 16B chunks per row
            cp16(stg + (A_OFF + row * LD_W + cc * 4) * 4,
                 A + (long long)(m0 + row) * K + k0 + cc * 4);
            cp16(stg + (B_OFF + row * LD_W + cc * 4) * 4,
                 B + (long long)(n0 + row) * K + k0 + cc * 4);
        }
    };

#pragma unroll
    for (int it = 0; it < STAGES - 1; it++) {
        issue_loads(it);
        CP_COMMIT();
    }

    for (int it = 0; it < niter; it++) {
        CP_WAIT(STAGES - 2);
        __syncthreads();
        if (it + STAGES - 1 < niter) issue_loads(it + STAGES - 1);
        CP_COMMIT();

        const int sw0 = (it % STAGES) * STAGE_W;

#pragma unroll
        for (int kk = 0; kk < BK; kk += 16) {
            uint32_t Ah[2][4], Al[2][4];
#pragma unroll
            for (int i = 0; i < 2; i++) {
                const int r = wm + i * 16 + g;
                const int base = sw0 + A_OFF + r * LD_W + kk + 2 * t;
                uint2 e  = *(const uint2*)(smw + base);
                uint2 f  = *(const uint2*)(smw + base + 8 * LD_W);
                uint2 p  = *(const uint2*)(smw + base + 8);
                uint2 q2 = *(const uint2*)(smw + base + 8 * LD_W + 8);
                Ah[i][0] = __byte_perm(e.x,  e.y,  0x5410); Al[i][0] = __byte_perm(e.x,  e.y,  0x7632);
                Ah[i][1] = __byte_perm(f.x,  f.y,  0x5410); Al[i][1] = __byte_perm(f.x,  f.y,  0x7632);
                Ah[i][2] = __byte_perm(p.x,  p.y,  0x5410); Al[i][2] = __byte_perm(p.x,  p.y,  0x7632);
                Ah[i][3] = __byte_perm(q2.x, q2.y, 0x5410); Al[i][3] = __byte_perm(q2.x, q2.y, 0x7632);
            }
#pragma unroll
            for (int j = 0; j < 8; j++) {
                const int n = wn + j * 8 + g;
                const int nb = sw0 + B_OFF + n * LD_W + kk + 2 * t;
                uint2 e = *(const uint2*)(smw + nb);
                uint2 f = *(const uint2*)(smw + nb + 8);
                uint32_t Bh[2] = {__byte_perm(e.x, e.y, 0x5410), __byte_perm(f.x, f.y, 0x5410)};
                uint32_t Bl[2] = {__byte_perm(e.x, e.y, 0x7632), __byte_perm(f.x, f.y, 0x7632)};
#pragma unroll
                for (int i = 0; i < 2; i++) {
                    mma_bf16(acc[i][j], Ah[i], Bh);
                    mma_bf16(acc[i][j], Ah[i], Bl);
                    mma_bf16(acc[i][j], Al[i], Bh);
                }
            }
        }
    }

    // -------- epilogue --------
#pragma unroll
    for (int i = 0; i < 2; i++) {
        const int r0 = m0 + wm + i * 16 + g;
#pragma unroll
        for (int j = 0; j < 8; j++) {
            const int cc = n0 + wn + j * 8 + 2 * t;
            float x0 = acc[i][j][0], x1 = acc[i][j][1];
            float x2 = acc[i][j][2], x3 = acc[i][j][3];
            if (BIAS) {
                float b0 = bias[cc], b1 = bias[cc + 1];
                x0 += b0; x1 += b1; x2 += b0; x3 += b1;
            }
            if (RELU) {
                x0 = fmaxf(x0, 0.f); x1 = fmaxf(x1, 0.f);
                x2 = fmaxf(x2, 0.f); x3 = fmaxf(x3, 0.f);
            }
            if (OUTBF) {
                uint32_t* C = (uint32_t*)Cv + (long long)blockIdx.z * sC;
                *(uint2*)(C + (long long)r0 * N + cc)       = make_uint2(bf_pack(x0), bf_pack(x1));
                *(uint2*)(C + (long long)(r0 + 8) * N + cc) = make_uint2(bf_pack(x2), bf_pack(x3));
            } else {
                float* C = (float*)Cv + (long long)blockIdx.z * sC;
                *(float2*)(C + (long long)r0 * N + cc)       = make_float2(x0, x1);
                *(float2*)(C + (long long)(r0 + 8) * N + cc) = make_float2(x2, x3);
            }
        }
    }
}

// ---------------------------------------------------------------------------
// pack fp32 -> bf-pair
// ---------------------------------------------------------------------------
__global__ __launch_bounds__(256) void pack_kernel(
    const float* __restrict__ in, uint32_t* __restrict__ out, int n4)
{
    int i = blockIdx.x * blockDim.x + threadIdx.x;
    for (; i < n4; i += gridDim.x * blockDim.x) {
        float4 v = ((const float4*)in)[i];
        uint4 w;
        w.x = bf_pack(v.x); w.y = bf_pack(v.y);
        w.z = bf_pack(v.z); w.w = bf_pack(v.w);
        ((uint4*)out)[i] = w;
    }
}

// ---------------------------------------------------------------------------
// transpose bf-pair v[b][n][h] -> vt[b][h][n]
// ---------------------------------------------------------------------------
__global__ __launch_bounds__(256) void transpose_kernel(
    const uint32_t* __restrict__ v, uint32_t* __restrict__ vt)
{
    __shared__ uint32_t tile[32][33];
    const int b = blockIdx.z;
    const int h0 = blockIdx.x * 32;
    const int n0 = blockIdx.y * 32;
    const int tx = threadIdx.x & 31;
    const int ty = threadIdx.x >> 5;

    const uint32_t* vb = v + (long long)b * NN * HH;
    uint32_t* vtb = vt + (long long)b * HH * NN;

#pragma unroll
    for (int j = 0; j < 32; j += 8)
        tile[ty + j][tx] = vb[(long long)(n0 + ty + j) * HH + h0 + tx];
    __syncthreads();
#pragma unroll
    for (int j = 0; j < 32; j += 8)
        vtb[(long long)(h0 + ty + j) * NN + n0 + tx] = tile[tx][ty + j];
}

// ---------------------------------------------------------------------------
// row softmax over bf-pair S rows of 1024
// ---------------------------------------------------------------------------
__global__ __launch_bounds__(256) void softmax_kernel(uint32_t* __restrict__ S)
{
    long long row = blockIdx.x;
    uint32_t* p = S + row * (long long)NN;
    int tid = threadIdx.x;
    uint4 w = ((uint4*)p)[tid];
    float x0 = bf_unpack(w.x), x1 = bf_unpack(w.y);
    float x2 = bf_unpack(w.z), x3 = bf_unpack(w.w);
    __shared__ float red[8];

    float m = fmaxf(fmaxf(x0, x1), fmaxf(x2, x3));
#pragma unroll
    for (int o = 16; o > 0; o >>= 1) m = fmaxf(m, __shfl_xor_sync(0xffffffffu, m, o));
    if ((tid & 31) == 0) red[tid >> 5] = m;
    __syncthreads();
    float bm = red[0];
#pragma unroll
    for (int i = 1; i < 8; i++) bm = fmaxf(bm, red[i]);
    __syncthreads();

    x0 = __expf(x0 - bm); x1 = __expf(x1 - bm);
    x2 = __expf(x2 - bm); x3 = __expf(x3 - bm);
    float s = x0 + x1 + x2 + x3;
#pragma unroll
    for (int o = 16; o > 0; o >>= 1) s += __shfl_xor_sync(0xffffffffu, s, o);
    if ((tid & 31) == 0) red[tid >> 5] = s;
    __syncthreads();
    float bs = red[0];
#pragma unroll
    for (int i = 1; i < 8; i++) bs += red[i];

    float inv = 1.0f / bs;
    w.x = bf_pack(x0 * inv); w.y = bf_pack(x1 * inv);
    w.z = bf_pack(x2 * inv); w.w = bf_pack(x3 * inv);
    ((uint4*)p)[tid] = w;
}

// ---------------------------------------------------------------------------
// kernel_launch — inputs: h, Wv, bv, Wk, bk, Wq, bq, Wo, bo
// ---------------------------------------------------------------------------
extern "C" void kernel_launch(void* const* d_in, const int* in_sizes, int n_in,
                              void* d_out, int out_size)
{
    const float* h  = (const float*)d_in[0];
    const float* Wv = (const float*)d_in[1];
    const float* bv = (const float*)d_in[2];
    const float* Wk = (const float*)d_in[3];
    const float* bk = (const float*)d_in[4];
    const float* Wq = (const float*)d_in[5];
    const float* bq = (const float*)d_in[6];
    const float* Wo = (const float*)d_in[7];
    const float* bo = (const float*)d_in[8];
    float* out = (float*)d_out;

    uint32_t *hb, *wq, *wk, *wv, *wo, *q, *k, *v, *vt, *s, *o;
    cudaGetSymbolAddress((void**)&hb, g_hb);
    cudaGetSymbolAddress((void**)&wq, g_wq);
    cudaGetSymbolAddress((void**)&wk, g_wk);
    cudaGetSymbolAddress((void**)&wv, g_wv);
    cudaGetSymbolAddress((void**)&wo, g_wo);
    cudaGetSymbolAddress((void**)&q,  g_q);
    cudaGetSymbolAddress((void**)&k,  g_k);
    cudaGetSymbolAddress((void**)&v,  g_v);
    cudaGetSymbolAddress((void**)&vt, g_vt);
    cudaGetSymbolAddress((void**)&s,  g_s);
    cudaGetSymbolAddress((void**)&o,  g_o);

    cudaFuncSetAttribute(tc_gemm<true, true, true>,
                         cudaFuncAttributeMaxDynamicSharedMemorySize, SMEM_BYTES);
    cudaFuncSetAttribute(tc_gemm<false, false, true>,
                         cudaFuncAttributeMaxDynamicSharedMemorySize, SMEM_BYTES);
    cudaFuncSetAttribute(tc_gemm<true, true, false>,
                         cudaFuncAttributeMaxDynamicSharedMemorySize, SMEM_BYTES);

    const int M = BB * NN;   // 32768

    // pack inputs to bf-pair
    pack_kernel<<<8192, 256>>>(h,  hb, BB * NN * DD / 4);
    pack_kernel<<<128,  256>>>(Wq, wq, HH * DD / 4);
    pack_kernel<<<128,  256>>>(Wk, wk, HH * DD / 4);
    pack_kernel<<<128,  256>>>(Wv, wv, HH * DD / 4);
    pack_kernel<<<128,  256>>>(Wo, wo, DD * HH / 4);

    // Q/K/V projections: relu(h Wx^T + bx) -> bf-pair [32768, 512]
    {
        dim3 grid(HH / BN, M / BM, 1);
        tc_gemm<true, true, true><<<grid, THREADS, SMEM_BYTES>>>(hb, wq, bq, q, M, HH, DD, 0, 0, 0);
        tc_gemm<true, true, true><<<grid, THREADS, SMEM_BYTES>>>(hb, wk, bk, k, M, HH, DD, 0, 0, 0);
        tc_gemm<true, true, true><<<grid, THREADS, SMEM_BYTES>>>(hb, wv, bv, v, M, HH, DD, 0, 0, 0);
    }

    // vt[b][h][n] = v[b][n][h]
    {
        dim3 grid(HH / 32, NN / 32, BB);
        transpose_kernel<<<grid, 256>>>(v, vt);
    }

    // S = Q K^T per batch
    {
        dim3 grid(NN / BN, NN / BM, BB);
        tc_gemm<false, false, true><<<grid, THREADS, SMEM_BYTES>>>(
            q, k, nullptr, s, NN, NN, HH,
            (long long)NN * HH, (long long)NN * HH, (long long)NN * NN);
    }

    softmax_kernel<<<BB * NN, 256>>>(s);

    // O = P Vt^T per batch
    {
        dim3 grid(HH / BN, NN / BM, BB);
        tc_gemm<false, false, true><<<grid, THREADS, SMEM_BYTES>>>(
            s, vt, nullptr, o, NN, HH, NN,
            (long long)NN * NN, (long long)HH * NN, (long long)NN * HH);
    }

    // out = relu(O Wo^T + bo) -> fp32
    {
        dim3 grid(DD / BN, M / BM, 1);
        tc_gemm<true, true, false><<<grid, THREADS, SMEM_BYTES>>>(o, wo, bo, out, M, DD, HH, 0, 0, 0);
    }
}

// round 5
// speedup vs baseline: 2.1589x; 1.0598x over previous
#include <cuda_runtime.h>
#include <cuda_bf16.h>
#include <cstdint>

// Problem dims
#define BB 32
#define NN 1024
#define DD 256
#define HH 512

// ---------------- two-plane bf16 scratch: [2][elems], plane 0 = hi, 1 = lo ---
#define HB_ELEMS (BB * NN * DD)
#define QKV_ELEMS (BB * NN * HH)
#define S_ELEMS ((long long)BB * NN * NN)
#define W1_ELEMS (HH * DD)
__device__ __nv_bfloat16 g_hb[2 * HB_ELEMS];
__device__ __nv_bfloat16 g_wq[2 * W1_ELEMS], g_wk[2 * W1_ELEMS], g_wv[2 * W1_ELEMS], g_wo[2 * W1_ELEMS];
__device__ __nv_bfloat16 g_q[2 * QKV_ELEMS];
__device__ __nv_bfloat16 g_k[2 * QKV_ELEMS];
__device__ __nv_bfloat16 g_v[2 * QKV_ELEMS];
__device__ __nv_bfloat16 g_vt[2 * QKV_ELEMS];           // [pl][b][h][n]
__device__ __nv_bfloat16 g_s[2 * S_ELEMS];
__device__ __nv_bfloat16 g_o[2 * QKV_ELEMS];

// ---------------- helpers ----------------
__device__ __forceinline__ void bf_split(float x, __nv_bfloat16& h, __nv_bfloat16& l) {
    h = __float2bfloat16_rn(x);
    l = __float2bfloat16_rn(x - __bfloat162float(h));
}
__device__ __forceinline__ uint32_t pack2(__nv_bfloat16 a, __nv_bfloat16 b) {
    __nv_bfloat162 t = __halves2bfloat162(a, b);
    return *reinterpret_cast<uint32_t*>(&t);
}
__device__ __forceinline__ uint32_t smem_u32(const void* p) {
    uint32_t a;
    asm("{ .reg .u64 t; cvta.to.shared.u64 t, %1; cvt.u32.u64 %0, t; }" : "=r"(a) : "l"(p));
    return a;
}
__device__ __forceinline__ void cp16(uint32_t dst, const void* src) {
    asm volatile("cp.async.cg.shared.global [%0], [%1], 16;" :: "r"(dst), "l"(src));
}
#define CP_COMMIT() asm volatile("cp.async.commit_group;" ::: "memory")
#define CP_WAIT(n)  asm volatile("cp.async.wait_group %0;" :: "n"(n) : "memory")

__device__ __forceinline__ void ldsm4(uint32_t* r, uint32_t addr) {
    asm volatile("ldmatrix.sync.aligned.m8n8.x4.shared.b16 {%0,%1,%2,%3}, [%4];"
        : "=r"(r[0]), "=r"(r[1]), "=r"(r[2]), "=r"(r[3]) : "r"(addr));
}
__device__ __forceinline__ void mma_bf16(float* d, const uint32_t* a, const uint32_t* b) {
    asm volatile(
        "mma.sync.aligned.m16n8k16.row.col.f32.bf16.bf16.f32 "
        "{%0,%1,%2,%3}, {%4,%5,%6,%7}, {%8,%9}, {%0,%1,%2,%3};"
        : "+f"(d[0]), "+f"(d[1]), "+f"(d[2]), "+f"(d[3])
        : "r"(a[0]), "r"(a[1]), "r"(a[2]), "r"(a[3]), "r"(b[0]), "r"(b[1]));
}

// ---------------- GEMM config ----------------
#define BM 128
#define BN 128
#define BK 32
#define STAGES 4
#define THREADS 256
#define LDP 40                            // bf16 pitch per smem row (80 B)
#define PLANE_B (128 * LDP * 2)           // 10240 B per plane tile
#define AH_OFF 0
#define AL_OFF PLANE_B
#define BH_OFF (2 * PLANE_B)
#define BL_OFF (3 * PLANE_B)
#define STAGE_BYTES (4 * PLANE_B)         // 40960
#define SMEM_BYTES (STAGES * STAGE_BYTES) // 163840

// ---------------------------------------------------------------------------
// NT GEMM on bf16-plane data: C = act(A * B^T + bias)
// A: M x K (hi plane at A, lo at A + sPA), B: N x K likewise. blockIdx.z batch.
// ---------------------------------------------------------------------------
template <bool BIAS, bool RELU, bool OUTBF>
__global__ __launch_bounds__(THREADS) void tc_gemm(
    const __nv_bfloat16* __restrict__ A, const __nv_bfloat16* __restrict__ B,
    const float* __restrict__ bias, void* __restrict__ Cv,
    int M, int N, int K,
    long long sA, long long sB, long long sC,
    long long sPA, long long sPB, long long sPC)
{
    extern __shared__ char smc[];
    const uint32_t sbase = smem_u32(smc);

    const int tid = threadIdx.x;
    const int wid = tid >> 5;
    const int lane = tid & 31;
    const int g = lane >> 2;
    const int t = lane & 3;

    const __nv_bfloat16* Ah = A + (long long)blockIdx.z * sA;
    const __nv_bfloat16* Al = Ah + sPA;
    const __nv_bfloat16* Bh = B + (long long)blockIdx.z * sB;
    const __nv_bfloat16* Bl = Bh + sPB;
    const int m0 = blockIdx.y * BM;
    const int n0 = blockIdx.x * BN;

    const int wm = (wid & 3) * 32;
    const int wn = (wid >> 2) * 64;

    float acc[2][8][4];
#pragma unroll
    for (int i = 0; i < 2; i++)
#pragma unroll
        for (int j = 0; j < 8; j++)
#pragma unroll
            for (int r = 0; r < 4; r++) acc[i][j][r] = 0.0f;

    const int niter = K / BK;

    // 2048 16B chunks per stage: seg 0=AH 1=AL 2=BH 3=BL, 512 chunks each
    auto issue_loads = [&](int it) {
        const int s = it % STAGES;
        const int k0 = it * BK;
        const uint32_t stg = sbase + s * STAGE_BYTES;
#pragma unroll
        for (int c = 0; c < 8; c++) {
            const int id = tid + c * 256;
            const int seg = id >> 9;
            const int rid = id & 511;
            const int row = rid >> 2, ch = rid & 3;
            const __nv_bfloat16* src;
            int grow;
            if (seg < 2) { src = (seg == 0) ? Ah : Al; grow = m0 + row; }
            else         { src = (seg == 2) ? Bh : Bl; grow = n0 + row; }
            cp16(stg + seg * PLANE_B + row * (LDP * 2) + ch * 16,
                 src + (long long)grow * K + k0 + ch * 8);
        }
    };

#pragma unroll
    for (int it = 0; it < STAGES - 1; it++) {
        issue_loads(it);
        CP_COMMIT();
    }

    // ldmatrix lane address components
    const int a_row = lane & 15;              // + wm + i*16
    const int a_kc  = (lane >> 4) * 8;        // + kk
    const int b_n   = ((lane >> 4) << 3) + (lane & 7);   // + wn + p*16
    const int b_kc  = ((lane >> 3) & 1) * 8;  // + kk

    for (int it = 0; it < niter; it++) {
        CP_WAIT(STAGES - 2);
        __syncthreads();
        if (it + STAGES - 1 < niter) issue_loads(it + STAGES - 1);
        CP_COMMIT();

        const uint32_t stg = sbase + (it % STAGES) * STAGE_BYTES;

#pragma unroll
        for (int kk = 0; kk < BK; kk += 16) {
            uint32_t Afh[2][4], Afl[2][4];
#pragma unroll
            for (int i = 0; i < 2; i++) {
                const uint32_t ao = (uint32_t)(wm + i * 16 + a_row) * (LDP * 2)
                                  + (uint32_t)(kk + a_kc) * 2;
                ldsm4(Afh[i], stg + AH_OFF + ao);
                ldsm4(Afl[i], stg + AL_OFF + ao);
            }
#pragma unroll
            for (int p = 0; p < 4; p++) {
                uint32_t Bfh[4], Bfl[4];
                const uint32_t bo = (uint32_t)(wn + p * 16 + b_n) * (LDP * 2)
                                  + (uint32_t)(kk + b_kc) * 2;
                ldsm4(Bfh, stg + BH_OFF + bo);
                ldsm4(Bfl, stg + BL_OFF + bo);
#pragma unroll
                for (int i = 0; i < 2; i++) {
                    mma_bf16(acc[i][2 * p],     Afh[i], &Bfh[0]);
                    mma_bf16(acc[i][2 * p],     Afh[i], &Bfl[0]);
                    mma_bf16(acc[i][2 * p],     Afl[i], &Bfh[0]);
                    mma_bf16(acc[i][2 * p + 1], Afh[i], &Bfh[2]);
                    mma_bf16(acc[i][2 * p + 1], Afh[i], &Bfl[2]);
                    mma_bf16(acc[i][2 * p + 1], Afl[i], &Bfh[2]);
                }
            }
        }
    }

    // -------- epilogue --------
#pragma unroll
    for (int i = 0; i < 2; i++) {
        const int r0 = m0 + wm + i * 16 + g;
#pragma unroll
        for (int j = 0; j < 8; j++) {
            const int cc = n0 + wn + j * 8 + 2 * t;
            float x0 = acc[i][j][0], x1 = acc[i][j][1];
            float x2 = acc[i][j][2], x3 = acc[i][j][3];
            if (BIAS) {
                float b0 = bias[cc], b1 = bias[cc + 1];
                x0 += b0; x1 += b1; x2 += b0; x3 += b1;
            }
            if (RELU) {
                x0 = fmaxf(x0, 0.f); x1 = fmaxf(x1, 0.f);
                x2 = fmaxf(x2, 0.f); x3 = fmaxf(x3, 0.f);
            }
            if (OUTBF) {
                __nv_bfloat16* Ch = (__nv_bfloat16*)Cv + (long long)blockIdx.z * sC;
                __nv_bfloat16* Cl = Ch + sPC;
                __nv_bfloat16 h0, l0, h1, l1, h2, l2, h3, l3;
                bf_split(x0, h0, l0); bf_split(x1, h1, l1);
                bf_split(x2, h2, l2); bf_split(x3, h3, l3);
                *(uint32_t*)(Ch + (long long)r0 * N + cc)       = pack2(h0, h1);
                *(uint32_t*)(Cl + (long long)r0 * N + cc)       = pack2(l0, l1);
                *(uint32_t*)(Ch + (long long)(r0 + 8) * N + cc) = pack2(h2, h3);
                *(uint32_t*)(Cl + (long long)(r0 + 8) * N + cc) = pack2(l2, l3);
            } else {
                float* C = (float*)Cv + (long long)blockIdx.z * sC;
                *(float2*)(C + (long long)r0 * N + cc)       = make_float2(x0, x1);
                *(float2*)(C + (long long)(r0 + 8) * N + cc) = make_float2(x2, x3);
            }
        }
    }
}

// ---------------------------------------------------------------------------
// pack fp32 -> two bf16 planes
// ---------------------------------------------------------------------------
__global__ __launch_bounds__(256) void pack_kernel(
    const float* __restrict__ in, __nv_bfloat16* __restrict__ hi,
    __nv_bfloat16* __restrict__ lo, int n4)
{
    int i = blockIdx.x * blockDim.x + threadIdx.x;
    for (; i < n4; i += gridDim.x * blockDim.x) {
        float4 v = ((const float4*)in)[i];
        __nv_bfloat16 h0, l0, h1, l1, h2, l2, h3, l3;
        bf_split(v.x, h0, l0); bf_split(v.y, h1, l1);
        bf_split(v.z, h2, l2); bf_split(v.w, h3, l3);
        uint2 wh = make_uint2(pack2(h0, h1), pack2(h2, h3));
        uint2 wl = make_uint2(pack2(l0, l1), pack2(l2, l3));
        ((uint2*)hi)[i] = wh;
        ((uint2*)lo)[i] = wl;
    }
}

// ---------------------------------------------------------------------------
// transpose per plane-batch: grid.z = 2*BB, in [z][n][h] -> out [z][h][n]
// ---------------------------------------------------------------------------
__global__ __launch_bounds__(256) void transpose_kernel(
    const __nv_bfloat16* __restrict__ v, __nv_bfloat16* __restrict__ vt)
{
    __shared__ __nv_bfloat16 tile[32][34];
    const int z = blockIdx.z;
    const int h0 = blockIdx.x * 32;
    const int n0 = blockIdx.y * 32;
    const int tx = threadIdx.x & 31;
    const int ty = threadIdx.x >> 5;

    const __nv_bfloat16* vb = v + (long long)z * NN * HH;
    __nv_bfloat16* vtb = vt + (long long)z * HH * NN;

#pragma unroll
    for (int j = 0; j < 32; j += 8)
        tile[ty + j][tx] = vb[(long long)(n0 + ty + j) * HH + h0 + tx];
    __syncthreads();
#pragma unroll
    for (int j = 0; j < 32; j += 8)
        vtb[(long long)(h0 + ty + j) * NN + n0 + tx] = tile[tx][ty + j];
}

// ---------------------------------------------------------------------------
// row softmax over plane-pair S rows of 1024
// ---------------------------------------------------------------------------
__global__ __launch_bounds__(256) void softmax_kernel(
    __nv_bfloat16* __restrict__ S, long long sP)
{
    long long row = blockIdx.x;
    __nv_bfloat16* ph = S + row * (long long)NN;
    __nv_bfloat16* pl = ph + sP;
    int tid = threadIdx.x;

    uint2 wh = ((uint2*)ph)[tid];
    uint2 wl = ((uint2*)pl)[tid];
    __nv_bfloat162 h01 = *reinterpret_cast<__nv_bfloat162*>(&wh.x);
    __nv_bfloat162 h23 = *reinterpret_cast<__nv_bfloat162*>(&wh.y);
    __nv_bfloat162 l01 = *reinterpret_cast<__nv_bfloat162*>(&wl.x);
    __nv_bfloat162 l23 = *reinterpret_cast<__nv_bfloat162*>(&wl.y);
    float x0 = __bfloat162float(__low2bfloat16(h01)) + __bfloat162float(__low2bfloat16(l01));
    float x1 = __bfloat162float(__high2bfloat16(h01)) + __bfloat162float(__high2bfloat16(l01));
    float x2 = __bfloat162float(__low2bfloat16(h23)) + __bfloat162float(__low2bfloat16(l23));
    float x3 = __bfloat162float(__high2bfloat16(h23)) + __bfloat162float(__high2bfloat16(l23));

    __shared__ float red[8];
    float m = fmaxf(fmaxf(x0, x1), fmaxf(x2, x3));
#pragma unroll
    for (int o = 16; o > 0; o >>= 1) m = fmaxf(m, __shfl_xor_sync(0xffffffffu, m, o));
    if ((tid & 31) == 0) red[tid >> 5] = m;
    __syncthreads();
    float bm = red[0];
#pragma unroll
    for (int i = 1; i < 8; i++) bm = fmaxf(bm, red[i]);
    __syncthreads();

    x0 = __expf(x0 - bm); x1 = __expf(x1 - bm);
    x2 = __expf(x2 - bm); x3 = __expf(x3 - bm);
    float s = x0 + x1 + x2 + x3;
#pragma unroll
    for (int o = 16; o > 0; o >>= 1) s += __shfl_xor_sync(0xffffffffu, s, o);
    if ((tid & 31) == 0) red[tid >> 5] = s;
    __syncthreads();
    float bs = red[0];
#pragma unroll
    for (int i = 1; i < 8; i++) bs += red[i];

    float inv = 1.0f / bs;
    x0 *= inv; x1 *= inv; x2 *= inv; x3 *= inv;
    __nv_bfloat16 h, l, h2, l2;
    bf_split(x0, h, l); bf_split(x1, h2, l2);
    wh.x = pack2(h, h2); wl.x = pack2(l, l2);
    bf_split(x2, h, l); bf_split(x3, h2, l2);
    wh.y = pack2(h, h2); wl.y = pack2(l, l2);
    ((uint2*)ph)[tid] = wh;
    ((uint2*)pl)[tid] = wl;
}

// ---------------------------------------------------------------------------
// kernel_launch — inputs: h, Wv, bv, Wk, bk, Wq, bq, Wo, bo
// ---------------------------------------------------------------------------
extern "C" void kernel_launch(void* const* d_in, const int* in_sizes, int n_in,
                              void* d_out, int out_size)
{
    const float* h  = (const float*)d_in[0];
    const float* Wv = (const float*)d_in[1];
    const float* bv = (const float*)d_in[2];
    const float* Wk = (const float*)d_in[3];
    const float* bk = (const float*)d_in[4];
    const float* Wq = (const float*)d_in[5];
    const float* bq = (const float*)d_in[6];
    const float* Wo = (const float*)d_in[7];
    const float* bo = (const float*)d_in[8];
    float* out = (float*)d_out;

    __nv_bfloat16 *hb, *wq, *wk, *wv, *wo, *q, *k, *v, *vt, *s, *o;
    cudaGetSymbolAddress((void**)&hb, g_hb);
    cudaGetSymbolAddress((void**)&wq, g_wq);
    cudaGetSymbolAddress((void**)&wk, g_wk);
    cudaGetSymbolAddress((void**)&wv, g_wv);
    cudaGetSymbolAddress((void**)&wo, g_wo);
    cudaGetSymbolAddress((void**)&q,  g_q);
    cudaGetSymbolAddress((void**)&k,  g_k);
    cudaGetSymbolAddress((void**)&v,  g_v);
    cudaGetSymbolAddress((void**)&vt, g_vt);
    cudaGetSymbolAddress((void**)&s,  g_s);
    cudaGetSymbolAddress((void**)&o,  g_o);

    cudaFuncSetAttribute(tc_gemm<true, true, true>,
                         cudaFuncAttributeMaxDynamicSharedMemorySize, SMEM_BYTES);
    cudaFuncSetAttribute(tc_gemm<false, false, true>,
                         cudaFuncAttributeMaxDynamicSharedMemorySize, SMEM_BYTES);
    cudaFuncSetAttribute(tc_gemm<true, true, false>,
                         cudaFuncAttributeMaxDynamicSharedMemorySize, SMEM_BYTES);

    const int M = BB * NN;   // 32768

    // pack inputs to planes
    pack_kernel<<<4096, 256>>>(h,  hb, hb + HB_ELEMS, HB_ELEMS / 4);
    pack_kernel<<<128,  256>>>(Wq, wq, wq + W1_ELEMS, W1_ELEMS / 4);
    pack_kernel<<<128,  256>>>(Wk, wk, wk + W1_ELEMS, W1_ELEMS / 4);
    pack_kernel<<<128,  256>>>(Wv, wv, wv + W1_ELEMS, W1_ELEMS / 4);
    pack_kernel<<<128,  256>>>(Wo, wo, wo + W1_ELEMS, W1_ELEMS / 4);

    // Q/K/V projections: relu(h Wx^T + bx) -> planes [32768, 512]
    {
        dim3 grid(HH / BN, M / BM, 1);
        tc_gemm<true, true, true><<<grid, THREADS, SMEM_BYTES>>>(
            hb, wq, bq, q, M, HH, DD, 0, 0, 0, HB_ELEMS, W1_ELEMS, QKV_ELEMS);
        tc_gemm<true, true, true><<<grid, THREADS, SMEM_BYTES>>>(
            hb, wk, bk, k, M, HH, DD, 0, 0, 0, HB_ELEMS, W1_ELEMS, QKV_ELEMS);
        tc_gemm<true, true, true><<<grid, THREADS, SMEM_BYTES>>>(
            hb, wv, bv, v, M, HH, DD, 0, 0, 0, HB_ELEMS, W1_ELEMS, QKV_ELEMS);
    }

    // vt[pl][b][h][n] = v[pl][b][n][h]
    {
        dim3 grid(HH / 32, NN / 32, 2 * BB);
        transpose_kernel<<<grid, 256>>>(v, vt);
    }

    // S = Q K^T per batch
    {
        dim3 grid(NN / BN, NN / BM, BB);
        tc_gemm<false, false, true><<<grid, THREADS, SMEM_BYTES>>>(
            q, k, nullptr, s, NN, NN, HH,
            (long long)NN * HH, (long long)NN * HH, (long long)NN * NN,
            QKV_ELEMS, QKV_ELEMS, S_ELEMS);
    }

    softmax_kernel<<<BB * NN, 256>>>(s, S_ELEMS);

    // O = P Vt^T per batch
    {
        dim3 grid(HH / BN, NN / BM, BB);
        tc_gemm<false, false, true><<<grid, THREADS, SMEM_BYTES>>>(
            s, vt, nullptr, o, NN, HH, NN,
            (long long)NN * NN, (long long)HH * NN, (long long)NN * HH,
            S_ELEMS, QKV_ELEMS, QKV_ELEMS);
    }

    // out = relu(O Wo^T + bo) -> fp32
    {
        dim3 grid(DD / BN, M / BM, 1);
        tc_gemm<true, true, false><<<grid, THREADS, SMEM_BYTES>>>(
            o, wo, bo, out, M, DD, HH, 0, 0, 0, QKV_ELEMS, W1_ELEMS, 0);
    }
}

// round 6
// speedup vs baseline: 3.1355x; 1.4524x over previous
#include <cuda_runtime.h>
#include <cuda_fp16.h>
#include <cstdint>

// Problem dims
#define BB 32
#define NN 1024
#define DD 256
#define HH 512
#define HB_ELEMS (BB * NN * DD)
#define QKV_ELEMS (BB * NN * HH)
#define S_ELEMS ((long long)BB * NN * NN)
#define W1_ELEMS (HH * DD)

// ---------------- scratch ----------------
__device__ __half g_h16[HB_ELEMS];
__device__ __half g_wq16[W1_ELEMS], g_wk16[W1_ELEMS], g_wv16[W1_ELEMS];
__device__ __half g_wo2[2 * W1_ELEMS];          // pair: hi plane, lo plane
__device__ __half g_q[QKV_ELEMS], g_k[QKV_ELEMS], g_v[QKV_ELEMS];
__device__ __half g_vt[QKV_ELEMS];              // [b][h][n]
__device__ float  g_sf[S_ELEMS];                // logits fp32 (134 MB)
__device__ __half g_p[S_ELEMS];                 // softmax probs fp16 (67 MB)
__device__ __half g_o2[2 * QKV_ELEMS];          // o pair

// ---------------- helpers ----------------
__device__ __forceinline__ void h_split(float x, __half& h, __half& l) {
    h = __float2half_rn(x);
    l = __float2half_rn(x - __half2float(h));
}
__device__ __forceinline__ uint32_t packh2(__half a, __half b) {
    __half2 t = __halves2half2(a, b);
    return *reinterpret_cast<uint32_t*>(&t);
}
__device__ __forceinline__ uint32_t smem_u32(const void* p) {
    uint32_t a;
    asm("{ .reg .u64 t; cvta.to.shared.u64 t, %1; cvt.u32.u64 %0, t; }" : "=r"(a) : "l"(p));
    return a;
}
__device__ __forceinline__ void cp16(uint32_t dst, const void* src) {
    asm volatile("cp.async.cg.shared.global [%0], [%1], 16;" :: "r"(dst), "l"(src));
}
#define CP_COMMIT() asm volatile("cp.async.commit_group;" ::: "memory")
#define CP_WAIT(n)  asm volatile("cp.async.wait_group %0;" :: "n"(n) : "memory")

__device__ __forceinline__ void ldsm4(uint32_t* r, uint32_t addr) {
    asm volatile("ldmatrix.sync.aligned.m8n8.x4.shared.b16 {%0,%1,%2,%3}, [%4];"
        : "=r"(r[0]), "=r"(r[1]), "=r"(r[2]), "=r"(r[3]) : "r"(addr));
}
__device__ __forceinline__ void mma_f16(float* d, const uint32_t* a, const uint32_t* b) {
    asm volatile(
        "mma.sync.aligned.m16n8k16.row.col.f32.f16.f16.f32 "
        "{%0,%1,%2,%3}, {%4,%5,%6,%7}, {%8,%9}, {%0,%1,%2,%3};"
        : "+f"(d[0]), "+f"(d[1]), "+f"(d[2]), "+f"(d[3])
        : "r"(a[0]), "r"(a[1]), "r"(a[2]), "r"(a[3]), "r"(b[0]), "r"(b[1]));
}

// ---------------- tile config ----------------
#define BM 128
#define BN 128
#define BK 32
#define THREADS 256
#define LDP 40                          // halves per smem row (80 B pitch)
#define PLANE_B (128 * LDP * 2)         // 10240 B per plane tile

// single-plane GEMM: 2 planes (A,B), 5 stages, 2 CTAs/SM
#define SSTAGES 5
#define SSTAGE_B (2 * PLANE_B)          // 20480
#define SSMEM (SSTAGES * SSTAGE_B)      // 102400

// pair GEMM: 4 planes, 3 stages
#define PSTAGES 3
#define PSTAGE_B (4 * PLANE_B)          // 40960
#define PSMEM (PSTAGES * PSTAGE_B)      // 122880

// ===========================================================================
// Single-plane fp16 NT GEMM (1 MMA): C = epi(A * B^T [+ bias])
// EPI: 0 = half out + bias + relu, 1 = fp32 out plain, 2 = half-pair out plain
// ===========================================================================
template <int EPI>
__global__ __launch_bounds__(THREADS, 2) void gemm_s(
    const __half* __restrict__ A, const __half* __restrict__ B,
    const float* __restrict__ bias, void* __restrict__ Cv,
    int M, int N, int K,
    long long sA, long long sB, long long sC, long long sPC)
{
    extern __shared__ char smc[];
    const uint32_t sbase = smem_u32(smc);

    const int tid = threadIdx.x;
    const int wid = tid >> 5;
    const int lane = tid & 31;
    const int g = lane >> 2;
    const int t = lane & 3;

    const __half* Ab = A + (long long)blockIdx.z * sA;
    const __half* Bb = B + (long long)blockIdx.z * sB;
    const int m0 = blockIdx.y * BM;
    const int n0 = blockIdx.x * BN;
    const int wm = (wid & 3) * 32;
    const int wn = (wid >> 2) * 64;

    float acc[2][8][4];
#pragma unroll
    for (int i = 0; i < 2; i++)
#pragma unroll
        for (int j = 0; j < 8; j++)
#pragma unroll
            for (int r = 0; r < 4; r++) acc[i][j][r] = 0.0f;

    const int niter = K / BK;

    // 1024 chunks per stage: seg 0 = A, 1 = B; 512 chunks each
    auto issue_loads = [&](int it) {
        const int s = it % SSTAGES;
        const int k0 = it * BK;
        const uint32_t stg = sbase + s * SSTAGE_B;
#pragma unroll
        for (int c = 0; c < 4; c++) {
            const int id = tid + c * 256;
            const int seg = id >> 9;
            const int rid = id & 511;
            const int row = rid >> 2, ch = rid & 3;
            const __half* src = seg ? (Bb + (long long)(n0 + row) * K)
                                    : (Ab + (long long)(m0 + row) * K);
            cp16(stg + seg * PLANE_B + row * 80 + ch * 16, src + k0 + ch * 8);
        }
    };

#pragma unroll
    for (int it = 0; it < SSTAGES - 1; it++) {
        issue_loads(it);
        CP_COMMIT();
    }

    const int a_row = lane & 15;
    const int a_kc = (lane >> 4) * 8;
    const int b_n = ((lane >> 4) << 3) + (lane & 7);
    const int b_kc = ((lane >> 3) & 1) * 8;

    for (int it = 0; it < niter; it++) {
        CP_WAIT(SSTAGES - 2);
        __syncthreads();
        if (it + SSTAGES - 1 < niter) issue_loads(it + SSTAGES - 1);
        CP_COMMIT();

        const uint32_t stg = sbase + (it % SSTAGES) * SSTAGE_B;
#pragma unroll
        for (int kk = 0; kk < BK; kk += 16) {
            uint32_t Af[2][4];
#pragma unroll
            for (int i = 0; i < 2; i++)
                ldsm4(Af[i], stg + (uint32_t)(wm + i * 16 + a_row) * 80
                               + (uint32_t)(kk + a_kc) * 2);
#pragma unroll
            for (int p = 0; p < 4; p++) {
                uint32_t Bf[4];
                ldsm4(Bf, stg + PLANE_B + (uint32_t)(wn + p * 16 + b_n) * 80
                                        + (uint32_t)(kk + b_kc) * 2);
#pragma unroll
                for (int i = 0; i < 2; i++) {
                    mma_f16(acc[i][2 * p],     Af[i], &Bf[0]);
                    mma_f16(acc[i][2 * p + 1], Af[i], &Bf[2]);
                }
            }
        }
    }

    // -------- epilogue --------
#pragma unroll
    for (int i = 0; i < 2; i++) {
        const int r0 = m0 + wm + i * 16 + g;
#pragma unroll
        for (int j = 0; j < 8; j++) {
            const int cc = n0 + wn + j * 8 + 2 * t;
            float x0 = acc[i][j][0], x1 = acc[i][j][1];
            float x2 = acc[i][j][2], x3 = acc[i][j][3];
            if (EPI == 0) {
                float b0 = bias[cc], b1 = bias[cc + 1];
                x0 = fmaxf(x0 + b0, 0.f); x1 = fmaxf(x1 + b1, 0.f);
                x2 = fmaxf(x2 + b0, 0.f); x3 = fmaxf(x3 + b1, 0.f);
                __half* C = (__half*)Cv + (long long)blockIdx.z * sC;
                *(uint32_t*)(C + (long long)r0 * N + cc) =
                    packh2(__float2half_rn(x0), __float2half_rn(x1));
                *(uint32_t*)(C + (long long)(r0 + 8) * N + cc) =
                    packh2(__float2half_rn(x2), __float2half_rn(x3));
            } else if (EPI == 1) {
                float* C = (float*)Cv + (long long)blockIdx.z * sC;
                *(float2*)(C + (long long)r0 * N + cc)       = make_float2(x0, x1);
                *(float2*)(C + (long long)(r0 + 8) * N + cc) = make_float2(x2, x3);
            } else {
                __half* Ch = (__half*)Cv + (long long)blockIdx.z * sC;
                __half* Cl = Ch + sPC;
                __half h0, l0, h1, l1, h2, l2, h3, l3;
                h_split(x0, h0, l0); h_split(x1, h1, l1);
                h_split(x2, h2, l2); h_split(x3, h3, l3);
                *(uint32_t*)(Ch + (long long)r0 * N + cc)       = packh2(h0, h1);
                *(uint32_t*)(Cl + (long long)r0 * N + cc)       = packh2(l0, l1);
                *(uint32_t*)(Ch + (long long)(r0 + 8) * N + cc) = packh2(h2, h3);
                *(uint32_t*)(Cl + (long long)(r0 + 8) * N + cc) = packh2(l2, l3);
            }
        }
    }
}

// ===========================================================================
// Pair fp16 NT GEMM (3 MMAs): C = relu(A * B^T + bias), fp32 out
// A pair: hi at A, lo at A + sPA; B pair likewise.
// ===========================================================================
__global__ __launch_bounds__(THREADS) void gemm_p3(
    const __half* __restrict__ A, const __half* __restrict__ B,
    const float* __restrict__ bias, float* __restrict__ C,
    int M, int N, int K, long long sPA, long long sPB)
{
    extern __shared__ char smc[];
    const uint32_t sbase = smem_u32(smc);

    const int tid = threadIdx.x;
    const int wid = tid >> 5;
    const int lane = tid & 31;
    const int g = lane >> 2;
    const int t = lane & 3;

    const __half* Ah = A;
    const __half* Al = A + sPA;
    const __half* Bh = B;
    const __half* Bl = B + sPB;
    const int m0 = blockIdx.y * BM;
    const int n0 = blockIdx.x * BN;
    const int wm = (wid & 3) * 32;
    const int wn = (wid >> 2) * 64;

    float acc[2][8][4];
#pragma unroll
    for (int i = 0; i < 2; i++)
#pragma unroll
        for (int j = 0; j < 8; j++)
#pragma unroll
            for (int r = 0; r < 4; r++) acc[i][j][r] = 0.0f;

    const int niter = K / BK;

    // 2048 chunks per stage: seg 0=AH 1=AL 2=BH 3=BL
    auto issue_loads = [&](int it) {
        const int s = it % PSTAGES;
        const int k0 = it * BK;
        const uint32_t stg = sbase + s * PSTAGE_B;
#pragma unroll
        for (int c = 0; c < 8; c++) {
            const int id = tid + c * 256;
            const int seg = id >> 9;
            const int rid = id & 511;
            const int row = rid >> 2, ch = rid & 3;
            const __half* src;
            int grow;
            if (seg < 2) { src = (seg == 0) ? Ah : Al; grow = m0 + row; }
            else         { src = (seg == 2) ? Bh : Bl; grow = n0 + row; }
            cp16(stg + seg * PLANE_B + row * 80 + ch * 16,
                 src + (long long)grow * K + k0 + ch * 8);
        }
    };

#pragma unroll
    for (int it = 0; it < PSTAGES - 1; it++) {
        issue_loads(it);
        CP_COMMIT();
    }

    const int a_row = lane & 15;
    const int a_kc = (lane >> 4) * 8;
    const int b_n = ((lane >> 4) << 3) + (lane & 7);
    const int b_kc = ((lane >> 3) & 1) * 8;

    for (int it = 0; it < niter; it++) {
        CP_WAIT(PSTAGES - 2);
        __syncthreads();
        if (it + PSTAGES - 1 < niter) issue_loads(it + PSTAGES - 1);
        CP_COMMIT();

        const uint32_t stg = sbase + (it % PSTAGES) * PSTAGE_B;
#pragma unroll
        for (int kk = 0; kk < BK; kk += 16) {
            uint32_t Afh[2][4], Afl[2][4];
#pragma unroll
            for (int i = 0; i < 2; i++) {
                const uint32_t ao = (uint32_t)(wm + i * 16 + a_row) * 80
                                  + (uint32_t)(kk + a_kc) * 2;
                ldsm4(Afh[i], stg + ao);
                ldsm4(Afl[i], stg + PLANE_B + ao);
            }
#pragma unroll
            for (int p = 0; p < 4; p++) {
                uint32_t Bfh[4], Bfl[4];
                const uint32_t bo = (uint32_t)(wn + p * 16 + b_n) * 80
                                  + (uint32_t)(kk + b_kc) * 2;
                ldsm4(Bfh, stg + 2 * PLANE_B + bo);
                ldsm4(Bfl, stg + 3 * PLANE_B + bo);
#pragma unroll
                for (int i = 0; i < 2; i++) {
                    mma_f16(acc[i][2 * p],     Afh[i], &Bfh[0]);
                    mma_f16(acc[i][2 * p],     Afl[i], &Bfh[0]);
                    mma_f16(acc[i][2 * p],     Afh[i], &Bfl[0]);
                    mma_f16(acc[i][2 * p + 1], Afh[i], &Bfh[2]);
                    mma_f16(acc[i][2 * p + 1], Afl[i], &Bfh[2]);
                    mma_f16(acc[i][2 * p + 1], Afh[i], &Bfl[2]);
                }
            }
        }
    }

#pragma unroll
    for (int i = 0; i < 2; i++) {
        const int r0 = m0 + wm + i * 16 + g;
#pragma unroll
        for (int j = 0; j < 8; j++) {
            const int cc = n0 + wn + j * 8 + 2 * t;
            float b0 = bias[cc], b1 = bias[cc + 1];
            float x0 = fmaxf(acc[i][j][0] + b0, 0.f);
            float x1 = fmaxf(acc[i][j][1] + b1, 0.f);
            float x2 = fmaxf(acc[i][j][2] + b0, 0.f);
            float x3 = fmaxf(acc[i][j][3] + b1, 0.f);
            *(float2*)(C + (long long)r0 * N + cc)       = make_float2(x0, x1);
            *(float2*)(C + (long long)(r0 + 8) * N + cc) = make_float2(x2, x3);
        }
    }
}

// ---------------------------------------------------------------------------
// pack fp32 -> fp16 single
// ---------------------------------------------------------------------------
__global__ __launch_bounds__(256) void pack_half(
    const float* __restrict__ in, __half* __restrict__ out, int n4)
{
    int i = blockIdx.x * blockDim.x + threadIdx.x;
    for (; i < n4; i += gridDim.x * blockDim.x) {
        float4 v = ((const float4*)in)[i];
        uint2 w;
        w.x = packh2(__float2half_rn(v.x), __float2half_rn(v.y));
        w.y = packh2(__float2half_rn(v.z), __float2half_rn(v.w));
        ((uint2*)out)[i] = w;
    }
}

// pack fp32 -> fp16 pair planes
__global__ __launch_bounds__(256) void pack_pair(
    const float* __restrict__ in, __half* __restrict__ hi,
    __half* __restrict__ lo, int n4)
{
    int i = blockIdx.x * blockDim.x + threadIdx.x;
    for (; i < n4; i += gridDim.x * blockDim.x) {
        float4 v = ((const float4*)in)[i];
        __half h0, l0, h1, l1, h2, l2, h3, l3;
        h_split(v.x, h0, l0); h_split(v.y, h1, l1);
        h_split(v.z, h2, l2); h_split(v.w, h3, l3);
        ((uint2*)hi)[i] = make_uint2(packh2(h0, h1), packh2(h2, h3));
        ((uint2*)lo)[i] = make_uint2(packh2(l0, l1), packh2(l2, l3));
    }
}

// ---------------------------------------------------------------------------
// transpose fp16 v[b][n][h] -> vt[b][h][n]
// ---------------------------------------------------------------------------
__global__ __launch_bounds__(256) void transpose_kernel(
    const __half* __restrict__ v, __half* __restrict__ vt)
{
    __shared__ __half tile[32][34];
    const int b = blockIdx.z;
    const int h0 = blockIdx.x * 32;
    const int n0 = blockIdx.y * 32;
    const int tx = threadIdx.x & 31;
    const int ty = threadIdx.x >> 5;

    const __half* vb = v + (long long)b * NN * HH;
    __half* vtb = vt + (long long)b * HH * NN;

#pragma unroll
    for (int j = 0; j < 32; j += 8)
        tile[ty + j][tx] = vb[(long long)(n0 + ty + j) * HH + h0 + tx];
    __syncthreads();
#pragma unroll
    for (int j = 0; j < 32; j += 8)
        vtb[(long long)(h0 + ty + j) * NN + n0 + tx] = tile[tx][ty + j];
}

// ---------------------------------------------------------------------------
// row softmax: fp32 logits in, fp16 probs out
// ---------------------------------------------------------------------------
__global__ __launch_bounds__(256) void softmax_kernel(
    const float* __restrict__ S, __half* __restrict__ P)
{
    long long row = blockIdx.x;
    const float* p = S + row * (long long)NN;
    __half* pp = P + row * (long long)NN;
    int tid = threadIdx.x;
    float4 v = ((const float4*)p)[tid];
    __shared__ float red[8];

    float m = fmaxf(fmaxf(v.x, v.y), fmaxf(v.z, v.w));
#pragma unroll
    for (int o = 16; o > 0; o >>= 1) m = fmaxf(m, __shfl_xor_sync(0xffffffffu, m, o));
    if ((tid & 31) == 0) red[tid >> 5] = m;
    __syncthreads();
    float bm = red[0];
#pragma unroll
    for (int i = 1; i < 8; i++) bm = fmaxf(bm, red[i]);
    __syncthreads();

    v.x = __expf(v.x - bm); v.y = __expf(v.y - bm);
    v.z = __expf(v.z - bm); v.w = __expf(v.w - bm);
    float s = v.x + v.y + v.z + v.w;
#pragma unroll
    for (int o = 16; o > 0; o >>= 1) s += __shfl_xor_sync(0xffffffffu, s, o);
    if ((tid & 31) == 0) red[tid >> 5] = s;
    __syncthreads();
    float bs = red[0];
#pragma unroll
    for (int i = 1; i < 8; i++) bs += red[i];

    float inv = 1.0f / bs;
    uint2 w;
    w.x = packh2(__float2half_rn(v.x * inv), __float2half_rn(v.y * inv));
    w.y = packh2(__float2half_rn(v.z * inv), __float2half_rn(v.w * inv));
    *(uint2*)(pp + tid * 4) = w;
}

// ---------------------------------------------------------------------------
// kernel_launch — inputs: h, Wv, bv, Wk, bk, Wq, bq, Wo, bo
// ---------------------------------------------------------------------------
extern "C" void kernel_launch(void* const* d_in, const int* in_sizes, int n_in,
                              void* d_out, int out_size)
{
    const float* h  = (const float*)d_in[0];
    const float* Wv = (const float*)d_in[1];
    const float* bv = (const float*)d_in[2];
    const float* Wk = (const float*)d_in[3];
    const float* bk = (const float*)d_in[4];
    const float* Wq = (const float*)d_in[5];
    const float* bq = (const float*)d_in[6];
    const float* Wo = (const float*)d_in[7];
    const float* bo = (const float*)d_in[8];
    float* out = (float*)d_out;

    __half *h16, *wq16, *wk16, *wv16, *wo2, *q, *k, *v, *vt, *p, *o2;
    float *sf;
    cudaGetSymbolAddress((void**)&h16,  g_h16);
    cudaGetSymbolAddress((void**)&wq16, g_wq16);
    cudaGetSymbolAddress((void**)&wk16, g_wk16);
    cudaGetSymbolAddress((void**)&wv16, g_wv16);
    cudaGetSymbolAddress((void**)&wo2,  g_wo2);
    cudaGetSymbolAddress((void**)&q,    g_q);
    cudaGetSymbolAddress((void**)&k,    g_k);
    cudaGetSymbolAddress((void**)&v,    g_v);
    cudaGetSymbolAddress((void**)&vt,   g_vt);
    cudaGetSymbolAddress((void**)&sf,   g_sf);
    cudaGetSymbolAddress((void**)&p,    g_p);
    cudaGetSymbolAddress((void**)&o2,   g_o2);

    cudaFuncSetAttribute(gemm_s<0>, cudaFuncAttributeMaxDynamicSharedMemorySize, SSMEM);
    cudaFuncSetAttribute(gemm_s<1>, cudaFuncAttributeMaxDynamicSharedMemorySize, SSMEM);
    cudaFuncSetAttribute(gemm_s<2>, cudaFuncAttributeMaxDynamicSharedMemorySize, SSMEM);
    cudaFuncSetAttribute(gemm_p3,  cudaFuncAttributeMaxDynamicSharedMemorySize, PSMEM);

    const int M = BB * NN;   // 32768

    // pack inputs
    pack_half<<<2048, 256>>>(h,  h16,  HB_ELEMS / 4);
    pack_half<<<128,  256>>>(Wq, wq16, W1_ELEMS / 4);
    pack_half<<<128,  256>>>(Wk, wk16, W1_ELEMS / 4);
    pack_half<<<128,  256>>>(Wv, wv16, W1_ELEMS / 4);
    pack_pair<<<128,  256>>>(Wo, wo2, wo2 + W1_ELEMS, W1_ELEMS / 4);

    // projections: relu(h W^T + b) -> fp16
    {
        dim3 grid(HH / BN, M / BM, 1);
        gemm_s<0><<<grid, THREADS, SSMEM>>>(h16, wq16, bq, q, M, HH, DD, 0, 0, 0, 0);
        gemm_s<0><<<grid, THREADS, SSMEM>>>(h16, wk16, bk, k, M, HH, DD, 0, 0, 0, 0);
        gemm_s<0><<<grid, THREADS, SSMEM>>>(h16, wv16, bv, v, M, HH, DD, 0, 0, 0, 0);
    }

    // vt[b][h][n] = v[b][n][h]
    {
        dim3 grid(HH / 32, NN / 32, BB);
        transpose_kernel<<<grid, 256>>>(v, vt);
    }

    // S = Q K^T per batch -> fp32 logits
    {
        dim3 grid(NN / BN, NN / BM, BB);
        gemm_s<1><<<grid, THREADS, SSMEM>>>(
            q, k, nullptr, sf, NN, NN, HH,
            (long long)NN * HH, (long long)NN * HH, (long long)NN * NN, 0);
    }

    // softmax -> fp16 probs
    softmax_kernel<<<BB * NN, 256>>>(sf, p);

    // O = P Vt^T per batch -> fp16 pair
    {
        dim3 grid(HH / BN, NN / BM, BB);
        gemm_s<2><<<grid, THREADS, SSMEM>>>(
            p, vt, nullptr, o2, NN, HH, NN,
            (long long)NN * NN, (long long)HH * NN, (long long)NN * HH, QKV_ELEMS);
    }

    // out = relu(O Wo^T + bo) -> fp32, full-precision pair GEMM
    {
        dim3 grid(DD / BN, M / BM, 1);
        gemm_p3<<<grid, THREADS, PSMEM>>>(o2, wo2, bo, out, M, DD, HH,
                                          QKV_ELEMS, W1_ELEMS);
    }
}

// round 7
// speedup vs baseline: 5.0511x; 1.6109x over previous
#include <cuda_runtime.h>
#include <cuda_fp16.h>
#include <cstdint>

// Problem dims
#define BB 32
#define NN 1024
#define DD 256
#define HH 512
#define HB_ELEMS (BB * NN * DD)
#define QKV_ELEMS (BB * NN * HH)
#define S_ELEMS ((long long)BB * NN * NN)
#define W1_ELEMS (HH * DD)
#define NTILE 8                          // 1024 keys / 128 per S col-tile

// ---------------- scratch ----------------
__device__ __half g_h16[HB_ELEMS];
__device__ __half g_wq16[W1_ELEMS], g_wk16[W1_ELEMS], g_wv16[W1_ELEMS];
__device__ __half g_wo2[2 * W1_ELEMS];          // pair: hi, lo planes
__device__ __half g_q[QKV_ELEMS], g_k[QKV_ELEMS], g_v[QKV_ELEMS];
__device__ __half g_vt[QKV_ELEMS];              // [b][h][n]
__device__ __half g_e[S_ELEMS];                 // exp(s - m_tile), fp16 (67 MB)
__device__ float  g_mloc[BB * NTILE * NN];      // per (b,tile,row) tile max
__device__ float  g_rsum[BB * NTILE * NN];      // per (b,tile,row) tile sum
__device__ float  g_scl[BB * NTILE * NN];       // per (b,tile,row) final scale
__device__ __half g_o2[2 * QKV_ELEMS];          // o pair

// ---------------- helpers ----------------
__device__ __forceinline__ void h_split(float x, __half& h, __half& l) {
    h = __float2half_rn(x);
    l = __float2half_rn(x - __half2float(h));
}
__device__ __forceinline__ uint32_t packh2(__half a, __half b) {
    __half2 t = __halves2half2(a, b);
    return *reinterpret_cast<uint32_t*>(&t);
}
__device__ __forceinline__ uint32_t mulh2(uint32_t a, __half2 s) {
    __half2 x = *reinterpret_cast<__half2*>(&a);
    x = __hmul2(x, s);
    return *reinterpret_cast<uint32_t*>(&x);
}
__device__ __forceinline__ uint32_t smem_u32(const void* p) {
    uint32_t a;
    asm("{ .reg .u64 t; cvta.to.shared.u64 t, %1; cvt.u32.u64 %0, t; }" : "=r"(a) : "l"(p));
    return a;
}
__device__ __forceinline__ void cp16(uint32_t dst, const void* src) {
    asm volatile("cp.async.cg.shared.global [%0], [%1], 16;" :: "r"(dst), "l"(src));
}
#define CP_COMMIT() asm volatile("cp.async.commit_group;" ::: "memory")
#define CP_WAIT(n)  asm volatile("cp.async.wait_group %0;" :: "n"(n) : "memory")

__device__ __forceinline__ void ldsm4(uint32_t* r, uint32_t addr) {
    asm volatile("ldmatrix.sync.aligned.m8n8.x4.shared.b16 {%0,%1,%2,%3}, [%4];"
        : "=r"(r[0]), "=r"(r[1]), "=r"(r[2]), "=r"(r[3]) : "r"(addr));
}
__device__ __forceinline__ void mma_f16(float* d, const uint32_t* a, const uint32_t* b) {
    asm volatile(
        "mma.sync.aligned.m16n8k16.row.col.f32.f16.f16.f32 "
        "{%0,%1,%2,%3}, {%4,%5,%6,%7}, {%8,%9}, {%0,%1,%2,%3};"
        : "+f"(d[0]), "+f"(d[1]), "+f"(d[2]), "+f"(d[3])
        : "r"(a[0]), "r"(a[1]), "r"(a[2]), "r"(a[3]), "r"(b[0]), "r"(b[1]));
}

// ---------------- tile config ----------------
#define BM 128
#define BN 128
#define BK 32
#define THREADS 256
#define PLANE_B (128 * 40 * 2)          // 10240 B (80 B pitch)

#define SSTAGES 5
#define SSTAGE_B (2 * PLANE_B)
#define SSMEM (SSTAGES * SSTAGE_B)      // 102400

#define PSTAGES 3
#define PSTAGE_B (4 * PLANE_B)
#define PSMEM (PSTAGES * PSTAGE_B)      // 122880

// ===========================================================================
// Single-plane fp16 NT GEMM: C = epi(A * B^T [+ bias])
// EPI: 0 = half out + bias + relu;  2 = half-pair out plain
// ===========================================================================
template <int EPI>
__global__ __launch_bounds__(THREADS, 2) void gemm_s(
    const __half* __restrict__ A, const __half* __restrict__ B,
    const float* __restrict__ bias, void* __restrict__ Cv,
    int M, int N, int K,
    long long sA, long long sB, long long sC, long long sPC)
{
    extern __shared__ char smc[];
    const uint32_t sbase = smem_u32(smc);

    const int tid = threadIdx.x;
    const int wid = tid >> 5;
    const int lane = tid & 31;
    const int g = lane >> 2;
    const int t = lane & 3;

    const __half* Ab = A + (long long)blockIdx.z * sA;
    const __half* Bb = B + (long long)blockIdx.z * sB;
    const int m0 = blockIdx.y * BM;
    const int n0 = blockIdx.x * BN;
    const int wm = (wid & 3) * 32;
    const int wn = (wid >> 2) * 64;

    float acc[2][8][4];
#pragma unroll
    for (int i = 0; i < 2; i++)
#pragma unroll
        for (int j = 0; j < 8; j++)
#pragma unroll
            for (int r = 0; r < 4; r++) acc[i][j][r] = 0.0f;

    const int niter = K / BK;

    auto issue_loads = [&](int it) {
        const int s = it % SSTAGES;
        const int k0 = it * BK;
        const uint32_t stg = sbase + s * SSTAGE_B;
#pragma unroll
        for (int c = 0; c < 4; c++) {
            const int id = tid + c * 256;
            const int seg = id >> 9;
            const int rid = id & 511;
            const int row = rid >> 2, ch = rid & 3;
            const __half* src = seg ? (Bb + (long long)(n0 + row) * K)
                                    : (Ab + (long long)(m0 + row) * K);
            cp16(stg + seg * PLANE_B + row * 80 + ch * 16, src + k0 + ch * 8);
        }
    };

#pragma unroll
    for (int it = 0; it < SSTAGES - 1; it++) { issue_loads(it); CP_COMMIT(); }

    const int a_row = lane & 15;
    const int a_kc = (lane >> 4) * 8;
    const int b_n = ((lane >> 4) << 3) + (lane & 7);
    const int b_kc = ((lane >> 3) & 1) * 8;

    for (int it = 0; it < niter; it++) {
        CP_WAIT(SSTAGES - 2);
        __syncthreads();
        if (it + SSTAGES - 1 < niter) issue_loads(it + SSTAGES - 1);
        CP_COMMIT();

        const uint32_t stg = sbase + (it % SSTAGES) * SSTAGE_B;
#pragma unroll
        for (int kk = 0; kk < BK; kk += 16) {
            uint32_t Af[2][4];
#pragma unroll
            for (int i = 0; i < 2; i++)
                ldsm4(Af[i], stg + (uint32_t)(wm + i * 16 + a_row) * 80
                               + (uint32_t)(kk + a_kc) * 2);
#pragma unroll
            for (int p = 0; p < 4; p++) {
                uint32_t Bf[4];
                ldsm4(Bf, stg + PLANE_B + (uint32_t)(wn + p * 16 + b_n) * 80
                                        + (uint32_t)(kk + b_kc) * 2);
#pragma unroll
                for (int i = 0; i < 2; i++) {
                    mma_f16(acc[i][2 * p],     Af[i], &Bf[0]);
                    mma_f16(acc[i][2 * p + 1], Af[i], &Bf[2]);
                }
            }
        }
    }

#pragma unroll
    for (int i = 0; i < 2; i++) {
        const int r0 = m0 + wm + i * 16 + g;
#pragma unroll
        for (int j = 0; j < 8; j++) {
            const int cc = n0 + wn + j * 8 + 2 * t;
            float x0 = acc[i][j][0], x1 = acc[i][j][1];
            float x2 = acc[i][j][2], x3 = acc[i][j][3];
            if (EPI == 0) {
                float b0 = bias[cc], b1 = bias[cc + 1];
                x0 = fmaxf(x0 + b0, 0.f); x1 = fmaxf(x1 + b1, 0.f);
                x2 = fmaxf(x2 + b0, 0.f); x3 = fmaxf(x3 + b1, 0.f);
                __half* C = (__half*)Cv + (long long)blockIdx.z * sC;
                *(uint32_t*)(C + (long long)r0 * N + cc) =
                    packh2(__float2half_rn(x0), __float2half_rn(x1));
                *(uint32_t*)(C + (long long)(r0 + 8) * N + cc) =
                    packh2(__float2half_rn(x2), __float2half_rn(x3));
            } else {
                __half* Ch = (__half*)Cv + (long long)blockIdx.z * sC;
                __half* Cl = Ch + sPC;
                __half h0, l0, h1, l1, h2, l2, h3, l3;
                h_split(x0, h0, l0); h_split(x1, h1, l1);
                h_split(x2, h2, l2); h_split(x3, h3, l3);
                *(uint32_t*)(Ch + (long long)r0 * N + cc)       = packh2(h0, h1);
                *(uint32_t*)(Cl + (long long)r0 * N + cc)       = packh2(l0, l1);
                *(uint32_t*)(Ch + (long long)(r0 + 8) * N + cc) = packh2(h2, h3);
                *(uint32_t*)(Cl + (long long)(r0 + 8) * N + cc) = packh2(l2, l3);
            }
        }
    }
}

// ===========================================================================
// S GEMM with online-exp epilogue: e = exp(s - rowmax_tile) -> fp16,
// plus per (row, tile) max/sum stats.
// ===========================================================================
__global__ __launch_bounds__(THREADS, 2) void gemm_qk(
    const __half* __restrict__ Q, const __half* __restrict__ Kx,
    __half* __restrict__ E, float* __restrict__ mloc, float* __restrict__ rsum)
{
    extern __shared__ char smc[];
    __shared__ float sred[2][128];
    const uint32_t sbase = smem_u32(smc);

    const int tid = threadIdx.x;
    const int wid = tid >> 5;
    const int lane = tid & 31;
    const int g = lane >> 2;
    const int t = lane & 3;
    const int bz = blockIdx.z;

    const __half* Ab = Q + ((long long)bz * NN * HH);
    const __half* Bb = Kx + ((long long)bz * NN * HH);
    const int m0 = blockIdx.y * BM;
    const int n0 = blockIdx.x * BN;
    const int wm = (wid & 3) * 32;
    const int wn = (wid >> 2) * 64;
    const int K = HH;

    float acc[2][8][4];
#pragma unroll
    for (int i = 0; i < 2; i++)
#pragma unroll
        for (int j = 0; j < 8; j++)
#pragma unroll
            for (int r = 0; r < 4; r++) acc[i][j][r] = 0.0f;

    const int niter = K / BK;

    auto issue_loads = [&](int it) {
        const int s = it % SSTAGES;
        const int k0 = it * BK;
        const uint32_t stg = sbase + s * SSTAGE_B;
#pragma unroll
        for (int c = 0; c < 4; c++) {
            const int id = tid + c * 256;
            const int seg = id >> 9;
            const int rid = id & 511;
            const int row = rid >> 2, ch = rid & 3;
            const __half* src = seg ? (Bb + (long long)(n0 + row) * K)
                                    : (Ab + (long long)(m0 + row) * K);
            cp16(stg + seg * PLANE_B + row * 80 + ch * 16, src + k0 + ch * 8);
        }
    };

#pragma unroll
    for (int it = 0; it < SSTAGES - 1; it++) { issue_loads(it); CP_COMMIT(); }

    const int a_row = lane & 15;
    const int a_kc = (lane >> 4) * 8;
    const int b_n = ((lane >> 4) << 3) + (lane & 7);
    const int b_kc = ((lane >> 3) & 1) * 8;

    for (int it = 0; it < niter; it++) {
        CP_WAIT(SSTAGES - 2);
        __syncthreads();
        if (it + SSTAGES - 1 < niter) issue_loads(it + SSTAGES - 1);
        CP_COMMIT();

        const uint32_t stg = sbase + (it % SSTAGES) * SSTAGE_B;
#pragma unroll
        for (int kk = 0; kk < BK; kk += 16) {
            uint32_t Af[2][4];
#pragma unroll
            for (int i = 0; i < 2; i++)
                ldsm4(Af[i], stg + (uint32_t)(wm + i * 16 + a_row) * 80
                               + (uint32_t)(kk + a_kc) * 2);
#pragma unroll
            for (int p = 0; p < 4; p++) {
                uint32_t Bf[4];
                ldsm4(Bf, stg + PLANE_B + (uint32_t)(wn + p * 16 + b_n) * 80
                                        + (uint32_t)(kk + b_kc) * 2);
#pragma unroll
                for (int i = 0; i < 2; i++) {
                    mma_f16(acc[i][2 * p],     Af[i], &Bf[0]);
                    mma_f16(acc[i][2 * p + 1], Af[i], &Bf[2]);
                }
            }
        }
    }

    // ---- online-exp epilogue ----
    // thread's 4 local rows
    const int R0 = wm + g, R1 = wm + g + 8, R2 = wm + 16 + g, R3 = wm + 24 + g;
    const int half = wid >> 2;

    // row max over this warp's 64 cols
    float rm[4] = {-1e30f, -1e30f, -1e30f, -1e30f};
#pragma unroll
    for (int j = 0; j < 8; j++) {
        rm[0] = fmaxf(rm[0], fmaxf(acc[0][j][0], acc[0][j][1]));
        rm[1] = fmaxf(rm[1], fmaxf(acc[0][j][2], acc[0][j][3]));
        rm[2] = fmaxf(rm[2], fmaxf(acc[1][j][0], acc[1][j][1]));
        rm[3] = fmaxf(rm[3], fmaxf(acc[1][j][2], acc[1][j][3]));
    }
#pragma unroll
    for (int o = 1; o <= 2; o <<= 1)
#pragma unroll
        for (int k = 0; k < 4; k++)
            rm[k] = fmaxf(rm[k], __shfl_xor_sync(0xffffffffu, rm[k], o));

    __syncthreads();            // mainloop smem quiesced; sred fresh
    if (t == 0) {
        sred[half][R0] = rm[0]; sred[half][R1] = rm[1];
        sred[half][R2] = rm[2]; sred[half][R3] = rm[3];
    }
    __syncthreads();
    float gm[4];
    gm[0] = fmaxf(sred[0][R0], sred[1][R0]);
    gm[1] = fmaxf(sred[0][R1], sred[1][R1]);
    gm[2] = fmaxf(sred[0][R2], sred[1][R2]);
    gm[3] = fmaxf(sred[0][R3], sred[1][R3]);
    __syncthreads();

    // exp + row sum
    float rs[4] = {0.f, 0.f, 0.f, 0.f};
#pragma unroll
    for (int j = 0; j < 8; j++) {
        acc[0][j][0] = __expf(acc[0][j][0] - gm[0]);
        acc[0][j][1] = __expf(acc[0][j][1] - gm[0]);
        rs[0] += acc[0][j][0] + acc[0][j][1];
        acc[0][j][2] = __expf(acc[0][j][2] - gm[1]);
        acc[0][j][3] = __expf(acc[0][j][3] - gm[1]);
        rs[1] += acc[0][j][2] + acc[0][j][3];
        acc[1][j][0] = __expf(acc[1][j][0] - gm[2]);
        acc[1][j][1] = __expf(acc[1][j][1] - gm[2]);
        rs[2] += acc[1][j][0] + acc[1][j][1];
        acc[1][j][2] = __expf(acc[1][j][2] - gm[3]);
        acc[1][j][3] = __expf(acc[1][j][3] - gm[3]);
        rs[3] += acc[1][j][2] + acc[1][j][3];
    }
#pragma unroll
    for (int o = 1; o <= 2; o <<= 1)
#pragma unroll
        for (int k = 0; k < 4; k++)
            rs[k] += __shfl_xor_sync(0xffffffffu, rs[k], o);

    if (t == 0) {
        if (half == 0) {
            sred[0][R0] = rs[0]; sred[0][R1] = rs[1];
            sred[0][R2] = rs[2]; sred[0][R3] = rs[3];
        }
    }
    __syncthreads();
    if (t == 0 && half == 1) {
        atomicAdd(&sred[0][R0], rs[0]); atomicAdd(&sred[0][R1], rs[1]);
        atomicAdd(&sred[0][R2], rs[2]); atomicAdd(&sred[0][R3], rs[3]);
    }
    __syncthreads();

    // stats write (warps 0-3, t==0 cover all 128 rows uniquely)
    if (t == 0 && half == 0) {
        const long long sb = ((long long)(bz * NTILE + blockIdx.x) << 10) + m0;
        mloc[sb + R0] = gm[0]; rsum[sb + R0] = sred[0][R0];
        mloc[sb + R1] = gm[1]; rsum[sb + R1] = sred[0][R1];
        mloc[sb + R2] = gm[2]; rsum[sb + R2] = sred[0][R2];
        mloc[sb + R3] = gm[3]; rsum[sb + R3] = sred[0][R3];
    }

    // e write
    __half* Eb = E + ((long long)bz << 20);
#pragma unroll
    for (int i = 0; i < 2; i++) {
        const int r0 = m0 + wm + i * 16 + g;
#pragma unroll
        for (int j = 0; j < 8; j++) {
            const int cc = n0 + wn + j * 8 + 2 * t;
            *(uint32_t*)(Eb + (long long)r0 * NN + cc) =
                packh2(__float2half_rn(acc[i][j][0]), __float2half_rn(acc[i][j][1]));
            *(uint32_t*)(Eb + (long long)(r0 + 8) * NN + cc) =
                packh2(__float2half_rn(acc[i][j][2]), __float2half_rn(acc[i][j][3]));
        }
    }
}

// ===========================================================================
// stats combine: scale_t(row) = exp(mloc_t - M) / denom
// ===========================================================================
__global__ __launch_bounds__(256) void stats_kernel(
    const float* __restrict__ mloc, const float* __restrict__ rsum,
    float* __restrict__ scl)
{
    const int idx = blockIdx.x * blockDim.x + threadIdx.x;   // 32768 rows
    const int b = idx >> 10, r = idx & 1023;
    float m[NTILE], s[NTILE];
    float M = -1e30f;
#pragma unroll
    for (int tt = 0; tt < NTILE; tt++) {
        const long long p = ((long long)(b * NTILE + tt) << 10) + r;
        m[tt] = mloc[p]; s[tt] = rsum[p];
        M = fmaxf(M, m[tt]);
    }
    float denom = 0.f;
#pragma unroll
    for (int tt = 0; tt < NTILE; tt++) {
        m[tt] = __expf(m[tt] - M);
        denom += s[tt] * m[tt];
    }
    const float inv = 1.0f / denom;
#pragma unroll
    for (int tt = 0; tt < NTILE; tt++)
        scl[((long long)(b * NTILE + tt) << 10) + r] = m[tt] * inv;
}

// ===========================================================================
// O GEMM: O = (diag-scaled E) * Vt^T, with per-(row, key-tile) fp16 scale
// applied to A fragments. Output: half-pair.
// ===========================================================================
__global__ __launch_bounds__(THREADS, 2) void gemm_pv(
    const __half* __restrict__ E, const __half* __restrict__ Vt,
    const float* __restrict__ scl, __half* __restrict__ O2, long long sPC)
{
    extern __shared__ char smc[];
    __shared__ float sscl[NTILE][128];
    const uint32_t sbase = smem_u32(smc);

    const int tid = threadIdx.x;
    const int wid = tid >> 5;
    const int lane = tid & 31;
    const int g = lane >> 2;
    const int t = lane & 3;
    const int bz = blockIdx.z;

    const __half* Ab = E + ((long long)bz << 20);                 // [1024][1024]
    const __half* Bb = Vt + ((long long)bz * HH * NN);            // [512][1024]
    const int m0 = blockIdx.y * BM;
    const int n0 = blockIdx.x * BN;
    const int wm = (wid & 3) * 32;
    const int wn = (wid >> 2) * 64;
    const int N = HH, K = NN;

    // preload scales for this CTA's 128 rows x 8 key-tiles
    for (int idx = tid; idx < NTILE * 128; idx += THREADS) {
        const int tt = idx >> 7, r = idx & 127;
        sscl[tt][r] = scl[((long long)(bz * NTILE + tt) << 10) + m0 + r];
    }

    float acc[2][8][4];
#pragma unroll
    for (int i = 0; i < 2; i++)
#pragma unroll
        for (int j = 0; j < 8; j++)
#pragma unroll
            for (int r = 0; r < 4; r++) acc[i][j][r] = 0.0f;

    const int niter = K / BK;     // 32

    auto issue_loads = [&](int it) {
        const int s = it % SSTAGES;
        const int k0 = it * BK;
        const uint32_t stg = sbase + s * SSTAGE_B;
#pragma unroll
        for (int c = 0; c < 4; c++) {
            const int id = tid + c * 256;
            const int seg = id >> 9;
            const int rid = id & 511;
            const int row = rid >> 2, ch = rid & 3;
            const __half* src = seg ? (Bb + (long long)(n0 + row) * K)
                                    : (Ab + (long long)(m0 + row) * K);
            cp16(stg + seg * PLANE_B + row * 80 + ch * 16, src + k0 + ch * 8);
        }
    };

#pragma unroll
    for (int it = 0; it < SSTAGES - 1; it++) { issue_loads(it); CP_COMMIT(); }
    __syncthreads();   // sscl ready

    const int a_row = lane & 15;
    const int a_kc = (lane >> 4) * 8;
    const int b_n = ((lane >> 4) << 3) + (lane & 7);
    const int b_kc = ((lane >> 3) & 1) * 8;

    const int R0 = wm + g, R1 = wm + g + 8, R2 = wm + 16 + g, R3 = wm + 24 + g;
    __half2 hs[4];

    for (int it = 0; it < niter; it++) {
        CP_WAIT(SSTAGES - 2);
        __syncthreads();
        if (it + SSTAGES - 1 < niter) issue_loads(it + SSTAGES - 1);
        CP_COMMIT();

        if ((it & 3) == 0) {
            const int tt = it >> 2;
            hs[0] = __float2half2_rn(sscl[tt][R0]);
            hs[1] = __float2half2_rn(sscl[tt][R1]);
            hs[2] = __float2half2_rn(sscl[tt][R2]);
            hs[3] = __float2half2_rn(sscl[tt][R3]);
        }

        const uint32_t stg = sbase + (it % SSTAGES) * SSTAGE_B;
#pragma unroll
        for (int kk = 0; kk < BK; kk += 16) {
            uint32_t Af[2][4];
#pragma unroll
            for (int i = 0; i < 2; i++) {
                ldsm4(Af[i], stg + (uint32_t)(wm + i * 16 + a_row) * 80
                               + (uint32_t)(kk + a_kc) * 2);
                Af[i][0] = mulh2(Af[i][0], hs[2 * i]);
                Af[i][1] = mulh2(Af[i][1], hs[2 * i + 1]);
                Af[i][2] = mulh2(Af[i][2], hs[2 * i]);
                Af[i][3] = mulh2(Af[i][3], hs[2 * i + 1]);
            }
#pragma unroll
            for (int p = 0; p < 4; p++) {
                uint32_t Bf[4];
                ldsm4(Bf, stg + PLANE_B + (uint32_t)(wn + p * 16 + b_n) * 80
                                        + (uint32_t)(kk + b_kc) * 2);
#pragma unroll
                for (int i = 0; i < 2; i++) {
                    mma_f16(acc[i][2 * p],     Af[i], &Bf[0]);
                    mma_f16(acc[i][2 * p + 1], Af[i], &Bf[2]);
                }
            }
        }
    }

    __half* Ch = O2 + (long long)bz * NN * HH;
    __half* Cl = Ch + sPC;
#pragma unroll
    for (int i = 0; i < 2; i++) {
        const int r0 = m0 + wm + i * 16 + g;
#pragma unroll
        for (int j = 0; j < 8; j++) {
            const int cc = n0 + wn + j * 8 + 2 * t;
            __half h0, l0, h1, l1, h2, l2, h3, l3;
            h_split(acc[i][j][0], h0, l0); h_split(acc[i][j][1], h1, l1);
            h_split(acc[i][j][2], h2, l2); h_split(acc[i][j][3], h3, l3);
            *(uint32_t*)(Ch + (long long)r0 * N + cc)       = packh2(h0, h1);
            *(uint32_t*)(Cl + (long long)r0 * N + cc)       = packh2(l0, l1);
            *(uint32_t*)(Ch + (long long)(r0 + 8) * N + cc) = packh2(h2, h3);
            *(uint32_t*)(Cl + (long long)(r0 + 8) * N + cc) = packh2(l2, l3);
        }
    }
}

// ===========================================================================
// Pair fp16 NT GEMM (3 MMAs): C = relu(A * B^T + bias), fp32 out
// ===========================================================================
__global__ __launch_bounds__(THREADS) void gemm_p3(
    const __half* __restrict__ A, const __half* __restrict__ B,
    const float* __restrict__ bias, float* __restrict__ C,
    int M, int N, int K, long long sPA, long long sPB)
{
    extern __shared__ char smc[];
    const uint32_t sbase = smem_u32(smc);

    const int tid = threadIdx.x;
    const int wid = tid >> 5;
    const int lane = tid & 31;
    const int g = lane >> 2;
    const int t = lane & 3;

    const __half* Ah = A;
    const __half* Al = A + sPA;
    const __half* Bh = B;
    const __half* Bl = B + sPB;
    const int m0 = blockIdx.y * BM;
    const int n0 = blockIdx.x * BN;
    const int wm = (wid & 3) * 32;
    const int wn = (wid >> 2) * 64;

    float acc[2][8][4];
#pragma unroll
    for (int i = 0; i < 2; i++)
#pragma unroll
        for (int j = 0; j < 8; j++)
#pragma unroll
            for (int r = 0; r < 4; r++) acc[i][j][r] = 0.0f;

    const int niter = K / BK;

    auto issue_loads = [&](int it) {
        const int s = it % PSTAGES;
        const int k0 = it * BK;
        const uint32_t stg = sbase + s * PSTAGE_B;
#pragma unroll
        for (int c = 0; c < 8; c++) {
            const int id = tid + c * 256;
            const int seg = id >> 9;
            const int rid = id & 511;
            const int row = rid >> 2, ch = rid & 3;
            const __half* src;
            int grow;
            if (seg < 2) { src = (seg == 0) ? Ah : Al; grow = m0 + row; }
            else         { src = (seg == 2) ? Bh : Bl; grow = n0 + row; }
            cp16(stg + seg * PLANE_B + row * 80 + ch * 16,
                 src + (long long)grow * K + k0 + ch * 8);
        }
    };

#pragma unroll
    for (int it = 0; it < PSTAGES - 1; it++) { issue_loads(it); CP_COMMIT(); }

    const int a_row = lane & 15;
    const int a_kc = (lane >> 4) * 8;
    const int b_n = ((lane >> 4) << 3) + (lane & 7);
    const int b_kc = ((lane >> 3) & 1) * 8;

    for (int it = 0; it < niter; it++) {
        CP_WAIT(PSTAGES - 2);
        __syncthreads();
        if (it + PSTAGES - 1 < niter) issue_loads(it + PSTAGES - 1);
        CP_COMMIT();

        const uint32_t stg = sbase + (it % PSTAGES) * PSTAGE_B;
#pragma unroll
        for (int kk = 0; kk < BK; kk += 16) {
            uint32_t Afh[2][4], Afl[2][4];
#pragma unroll
            for (int i = 0; i < 2; i++) {
                const uint32_t ao = (uint32_t)(wm + i * 16 + a_row) * 80
                                  + (uint32_t)(kk + a_kc) * 2;
                ldsm4(Afh[i], stg + ao);
                ldsm4(Afl[i], stg + PLANE_B + ao);
            }
#pragma unroll
            for (int p = 0; p < 4; p++) {
                uint32_t Bfh[4], Bfl[4];
                const uint32_t bo = (uint32_t)(wn + p * 16 + b_n) * 80
                                  + (uint32_t)(kk + b_kc) * 2;
                ldsm4(Bfh, stg + 2 * PLANE_B + bo);
                ldsm4(Bfl, stg + 3 * PLANE_B + bo);
#pragma unroll
                for (int i = 0; i < 2; i++) {
                    mma_f16(acc[i][2 * p],     Afh[i], &Bfh[0]);
                    mma_f16(acc[i][2 * p],     Afl[i], &Bfh[0]);
                    mma_f16(acc[i][2 * p],     Afh[i], &Bfl[0]);
                    mma_f16(acc[i][2 * p + 1], Afh[i], &Bfh[2]);
                    mma_f16(acc[i][2 * p + 1], Afl[i], &Bfh[2]);
                    mma_f16(acc[i][2 * p + 1], Afh[i], &Bfl[2]);
                }
            }
        }
    }

#pragma unroll
    for (int i = 0; i < 2; i++) {
        const int r0 = m0 + wm + i * 16 + g;
#pragma unroll
        for (int j = 0; j < 8; j++) {
            const int cc = n0 + wn + j * 8 + 2 * t;
            float b0 = bias[cc], b1 = bias[cc + 1];
            *(float2*)(C + (long long)r0 * N + cc) =
                make_float2(fmaxf(acc[i][j][0] + b0, 0.f), fmaxf(acc[i][j][1] + b1, 0.f));
            *(float2*)(C + (long long)(r0 + 8) * N + cc) =
                make_float2(fmaxf(acc[i][j][2] + b0, 0.f), fmaxf(acc[i][j][3] + b1, 0.f));
        }
    }
}

// ---------------------------------------------------------------------------
// fused pack: h->h16, Wq/Wk/Wv->fp16, Wo->pair
// ---------------------------------------------------------------------------
#define PK_H (HB_ELEMS / 4)
#define PK_W (W1_ELEMS / 4)
__global__ __launch_bounds__(256) void pack_all(
    const float* __restrict__ h, const float* __restrict__ Wq,
    const float* __restrict__ Wk, const float* __restrict__ Wv,
    const float* __restrict__ Wo,
    __half* __restrict__ h16, __half* __restrict__ wq16,
    __half* __restrict__ wk16, __half* __restrict__ wv16,
    __half* __restrict__ wo2)
{
    const int total = PK_H + 4 * PK_W;
    for (int i = blockIdx.x * blockDim.x + threadIdx.x; i < total;
         i += gridDim.x * blockDim.x) {
        if (i < PK_H + 3 * PK_W) {
            const float* src; __half* dst; int idx;
            if (i < PK_H) { src = h; dst = h16; idx = i; }
            else {
                int r = i - PK_H;
                int seg = r / PK_W; idx = r % PK_W;
                src = (seg == 0) ? Wq : (seg == 1) ? Wk : Wv;
                dst = (seg == 0) ? wq16 : (seg == 1) ? wk16 : wv16;
            }
            float4 v = ((const float4*)src)[idx];
            ((uint2*)dst)[idx] = make_uint2(
                packh2(__float2half_rn(v.x), __float2half_rn(v.y)),
                packh2(__float2half_rn(v.z), __float2half_rn(v.w)));
        } else {
            int idx = i - PK_H - 3 * PK_W;
            float4 v = ((const float4*)Wo)[idx];
            __half h0, l0, h1, l1, h2, l2, h3, l3;
            h_split(v.x, h0, l0); h_split(v.y, h1, l1);
            h_split(v.z, h2, l2); h_split(v.w, h3, l3);
            ((uint2*)wo2)[idx] = make_uint2(packh2(h0, h1), packh2(h2, h3));
            ((uint2*)(wo2 + 2 * W1_ELEMS))[idx] = make_uint2(packh2(l0, l1), packh2(l2, l3));
        }
    }
}

// ---------------------------------------------------------------------------
// transpose fp16 v[b][n][h] -> vt[b][h][n]
// ---------------------------------------------------------------------------
__global__ __launch_bounds__(256) void transpose_kernel(
    const __half* __restrict__ v, __half* __restrict__ vt)
{
    __shared__ __half tile[32][34];
    const int b = blockIdx.z;
    const int h0 = blockIdx.x * 32;
    const int n0 = blockIdx.y * 32;
    const int tx = threadIdx.x & 31;
    const int ty = threadIdx.x >> 5;

    const __half* vb = v + (long long)b * NN * HH;
    __half* vtb = vt + (long long)b * HH * NN;

#pragma unroll
    for (int j = 0; j < 32; j += 8)
        tile[ty + j][tx] = vb[(long long)(n0 + ty + j) * HH + h0 + tx];
    __syncthreads();
#pragma unroll
    for (int j = 0; j < 32; j += 8)
        vtb[(long long)(h0 + ty + j) * NN + n0 + tx] = tile[tx][ty + j];
}

// ---------------------------------------------------------------------------
// kernel_launch — inputs: h, Wv, bv, Wk, bk, Wq, bq, Wo, bo
// ---------------------------------------------------------------------------
extern "C" void kernel_launch(void* const* d_in, const int* in_sizes, int n_in,
                              void* d_out, int out_size)
{
    const float* h  = (const float*)d_in[0];
    const float* Wv = (const float*)d_in[1];
    const float* bv = (const float*)d_in[2];
    const float* Wk = (const float*)d_in[3];
    const float* bk = (const float*)d_in[4];
    const float* Wq = (const float*)d_in[5];
    const float* bq = (const float*)d_in[6];
    const float* Wo = (const float*)d_in[7];
    const float* bo = (const float*)d_in[8];
    float* out = (float*)d_out;

    __half *h16, *wq16, *wk16, *wv16, *wo2, *q, *k, *v, *vt, *e, *o2;
    float *mloc, *rsum, *scl;
    cudaGetSymbolAddress((void**)&h16,  g_h16);
    cudaGetSymbolAddress((void**)&wq16, g_wq16);
    cudaGetSymbolAddress((void**)&wk16, g_wk16);
    cudaGetSymbolAddress((void**)&wv16, g_wv16);
    cudaGetSymbolAddress((void**)&wo2,  g_wo2);
    cudaGetSymbolAddress((void**)&q,    g_q);
    cudaGetSymbolAddress((void**)&k,    g_k);
    cudaGetSymbolAddress((void**)&v,    g_v);
    cudaGetSymbolAddress((void**)&vt,   g_vt);
    cudaGetSymbolAddress((void**)&e,    g_e);
    cudaGetSymbolAddress((void**)&mloc, g_mloc);
    cudaGetSymbolAddress((void**)&rsum, g_rsum);
    cudaGetSymbolAddress((void**)&scl,  g_scl);
    cudaGetSymbolAddress((void**)&o2,   g_o2);

    cudaFuncSetAttribute(gemm_s<0>, cudaFuncAttributeMaxDynamicSharedMemorySize, SSMEM);
    cudaFuncSetAttribute(gemm_qk,   cudaFuncAttributeMaxDynamicSharedMemorySize, SSMEM);
    cudaFuncSetAttribute(gemm_pv,   cudaFuncAttributeMaxDynamicSharedMemorySize, SSMEM);
    cudaFuncSetAttribute(gemm_p3,   cudaFuncAttributeMaxDynamicSharedMemorySize, PSMEM);

    const int M = BB * NN;   // 32768

    // 1. fused pack
    pack_all<<<2048, 256>>>(h, Wq, Wk, Wv, Wo, h16, wq16, wk16, wv16, wo2);

    // 2-4. projections: relu(h W^T + b) -> fp16
    {
        dim3 grid(HH / BN, M / BM, 1);
        gemm_s<0><<<grid, THREADS, SSMEM>>>(h16, wq16, bq, q, M, HH, DD, 0, 0, 0, 0);
        gemm_s<0><<<grid, THREADS, SSMEM>>>(h16, wk16, bk, k, M, HH, DD, 0, 0, 0, 0);
        gemm_s<0><<<grid, THREADS, SSMEM>>>(h16, wv16, bv, v, M, HH, DD, 0, 0, 0, 0);
    }

    // 5. vt[b][h][n] = v[b][n][h]
    {
        dim3 grid(HH / 32, NN / 32, BB);
        transpose_kernel<<<grid, 256>>>(v, vt);
    }

    // 6. S GEMM + online exp -> e fp16 + per-tile stats
    {
        dim3 grid(NN / BN, NN / BM, BB);
        gemm_qk<<<grid, THREADS, SSMEM>>>(q, k, e, mloc, rsum);
    }

    // 7. stats combine -> scales
    stats_kernel<<<M / 256, 256>>>(mloc, rsum, scl);

    // 8. O = scaled-E * Vt^T -> fp16 pair
    {
        dim3 grid(HH / BN, NN / BM, BB);
        gemm_pv<<<grid, THREADS, SSMEM>>>(e, vt, scl, o2, QKV_ELEMS);
    }

    // 9. out = relu(O Wo^T + bo) -> fp32
    {
        dim3 grid(DD / BN, M / BM, 1);
        gemm_p3<<<grid, THREADS, PSMEM>>>(o2, wo2, bo, out, M, DD, HH,
                                          QKV_ELEMS, W1_ELEMS);
    }
}

// round 8
// speedup vs baseline: 5.4738x; 1.0837x over previous
#include <cuda_runtime.h>
#include <cuda_fp16.h>
#include <cstdint>

// Problem dims
#define BB 32
#define NN 1024
#define DD 256
#define HH 512
#define HB_ELEMS (BB * NN * DD)
#define QKV_ELEMS (BB * NN * HH)
#define S_ELEMS ((long long)BB * NN * NN)
#define W1_ELEMS (HH * DD)
#define NTILE 8                          // 1024 keys / 128 per S col-tile

// ---------------- scratch ----------------
__device__ __half g_h16[HB_ELEMS];
__device__ __half g_wq16[W1_ELEMS], g_wk16[W1_ELEMS], g_wv16[W1_ELEMS];
__device__ __half g_wo2[2 * W1_ELEMS];          // pair: hi, lo planes
__device__ __half g_q[QKV_ELEMS], g_k[QKV_ELEMS], g_v[QKV_ELEMS];
__device__ __half g_vt[QKV_ELEMS];              // [b][h][n]
__device__ __half g_e[S_ELEMS];                 // exp(s - m_tile), fp16
__device__ float  g_mloc[BB * NTILE * NN];
__device__ float  g_rsum[BB * NTILE * NN];
__device__ float  g_scl[BB * NTILE * NN];
__device__ __half g_o2[2 * QKV_ELEMS];          // o pair

// ---------------- helpers ----------------
__device__ __forceinline__ void h_split(float x, __half& h, __half& l) {
    h = __float2half_rn(x);
    l = __float2half_rn(x - __half2float(h));
}
__device__ __forceinline__ uint32_t packh2(__half a, __half b) {
    __half2 t = __halves2half2(a, b);
    return *reinterpret_cast<uint32_t*>(&t);
}
__device__ __forceinline__ uint32_t mulh2(uint32_t a, __half2 s) {
    __half2 x = *reinterpret_cast<__half2*>(&a);
    x = __hmul2(x, s);
    return *reinterpret_cast<uint32_t*>(&x);
}
__device__ __forceinline__ uint32_t smem_u32(const void* p) {
    uint32_t a;
    asm("{ .reg .u64 t; cvta.to.shared.u64 t, %1; cvt.u32.u64 %0, t; }" : "=r"(a) : "l"(p));
    return a;
}
__device__ __forceinline__ void cp16(uint32_t dst, const void* src) {
    asm volatile("cp.async.cg.shared.global [%0], [%1], 16;" :: "r"(dst), "l"(src));
}
#define CP_COMMIT() asm volatile("cp.async.commit_group;" ::: "memory")
#define CP_WAIT(n)  asm volatile("cp.async.wait_group %0;" :: "n"(n) : "memory")

__device__ __forceinline__ void ldsm4(uint32_t* r, uint32_t addr) {
    asm volatile("ldmatrix.sync.aligned.m8n8.x4.shared.b16 {%0,%1,%2,%3}, [%4];"
        : "=r"(r[0]), "=r"(r[1]), "=r"(r[2]), "=r"(r[3]) : "r"(addr));
}
__device__ __forceinline__ void mma_f16(float* d, const uint32_t* a, const uint32_t* b) {
    asm volatile(
        "mma.sync.aligned.m16n8k16.row.col.f32.f16.f16.f32 "
        "{%0,%1,%2,%3}, {%4,%5,%6,%7}, {%8,%9}, {%0,%1,%2,%3};"
        : "+f"(d[0]), "+f"(d[1]), "+f"(d[2]), "+f"(d[3])
        : "r"(a[0]), "r"(a[1]), "r"(a[2]), "r"(a[3]), "r"(b[0]), "r"(b[1]));
}

// ---------------- tile config ----------------
#define BM 128
#define BN 128
#define THREADS 256

// single-plane GEMMs: BK=64, pitch 72 halves (144 B), 3 stages, 2 CTAs/SM
#define BK64 64
#define PITCH64 144                      // bytes per row
#define PLANE64 (128 * PITCH64)          // 18432 B
#define SSTAGES 3
#define SSTAGE_B (2 * PLANE64)           // 36864
#define SSMEM (SSTAGES * SSTAGE_B)       // 110592

// pair GEMM (out-proj): BK=32, pitch 80 B, 3 stages
#define BK32 32
#define PLANE32 (128 * 80)               // 10240 B
#define PSTAGES 3
#define PSTAGE_B (4 * PLANE32)           // 40960
#define PSMEM (PSTAGES * PSTAGE_B)       // 122880

// ---- shared mainloop pieces (BK=64 single-plane) ----
// stage chunks: 2048 x 16B; seg = A/B plane, 8 chunks per 128B row of data
#define ISSUE64(Ab, Bb, Kdim, it)                                              \
    do {                                                                       \
        const int s_ = (it) % SSTAGES;                                         \
        const int k0_ = (it) * BK64;                                           \
        const uint32_t stg_ = sbase + s_ * SSTAGE_B;                           \
        _Pragma("unroll")                                                      \
        for (int c_ = 0; c_ < 8; c_++) {                                       \
            const int id_ = tid + c_ * 256;                                    \
            const int seg_ = id_ >> 10;                                        \
            const int rid_ = id_ & 1023;                                       \
            const int row_ = rid_ >> 3, ch_ = rid_ & 7;                        \
            const __half* src_ = seg_ ? (Bb + (long long)(n0 + row_) * Kdim)   \
                                      : (Ab + (long long)(m0 + row_) * Kdim);  \
            cp16(stg_ + seg_ * PLANE64 + row_ * PITCH64 + ch_ * 16,            \
                 src_ + k0_ + ch_ * 8);                                        \
        }                                                                      \
    } while (0)

// ===========================================================================
// Fused Q/K/V projection: grid.z selects (W, bias, dst)
// C = relu(h W^T + b) -> fp16 [32768, 512]
// ===========================================================================
__global__ __launch_bounds__(THREADS, 2) void gemm_proj(
    const __half* __restrict__ Hm,
    const __half* __restrict__ Wqp, const __half* __restrict__ Wkp,
    const __half* __restrict__ Wvp,
    const float* __restrict__ bqp, const float* __restrict__ bkp,
    const float* __restrict__ bvp,
    __half* __restrict__ Qp, __half* __restrict__ Kp, __half* __restrict__ Vp)
{
    extern __shared__ char smc[];
    const uint32_t sbase = smem_u32(smc);

    const int tid = threadIdx.x;
    const int wid = tid >> 5;
    const int lane = tid & 31;
    const int g = lane >> 2;
    const int t = lane & 3;
    const int z = blockIdx.z;

    const __half* Ab = Hm;
    const __half* Bb = (z == 0) ? Wqp : (z == 1) ? Wkp : Wvp;
    const float* bias = (z == 0) ? bqp : (z == 1) ? bkp : bvp;
    __half* C = (z == 0) ? Qp : (z == 1) ? Kp : Vp;

    const int m0 = blockIdx.y * BM;
    const int n0 = blockIdx.x * BN;
    const int wm = (wid & 3) * 32;
    const int wn = (wid >> 2) * 64;
    const int K = DD, N = HH;

    float acc[2][8][4];
#pragma unroll
    for (int i = 0; i < 2; i++)
#pragma unroll
        for (int j = 0; j < 8; j++)
#pragma unroll
            for (int r = 0; r < 4; r++) acc[i][j][r] = 0.0f;

    const int niter = K / BK64;     // 4

#pragma unroll
    for (int it = 0; it < SSTAGES - 1; it++) { ISSUE64(Ab, Bb, K, it); CP_COMMIT(); }

    const int a_row = lane & 15;
    const int a_kc = (lane >> 4) * 8;
    const int b_n = ((lane >> 4) << 3) + (lane & 7);
    const int b_kc = ((lane >> 3) & 1) * 8;

    for (int it = 0; it < niter; it++) {
        CP_WAIT(SSTAGES - 2);
        __syncthreads();
        if (it + SSTAGES - 1 < niter) { ISSUE64(Ab, Bb, K, it + SSTAGES - 1); }
        CP_COMMIT();

        const uint32_t stg = sbase + (it % SSTAGES) * SSTAGE_B;
#pragma unroll
        for (int kk = 0; kk < BK64; kk += 16) {
            uint32_t Af[2][4];
#pragma unroll
            for (int i = 0; i < 2; i++)
                ldsm4(Af[i], stg + (uint32_t)(wm + i * 16 + a_row) * PITCH64
                               + (uint32_t)(kk + a_kc) * 2);
#pragma unroll
            for (int p = 0; p < 4; p++) {
                uint32_t Bf[4];
                ldsm4(Bf, stg + PLANE64 + (uint32_t)(wn + p * 16 + b_n) * PITCH64
                                        + (uint32_t)(kk + b_kc) * 2);
#pragma unroll
                for (int i = 0; i < 2; i++) {
                    mma_f16(acc[i][2 * p],     Af[i], &Bf[0]);
                    mma_f16(acc[i][2 * p + 1], Af[i], &Bf[2]);
                }
            }
        }
    }

#pragma unroll
    for (int i = 0; i < 2; i++) {
        const int r0 = m0 + wm + i * 16 + g;
#pragma unroll
        for (int j = 0; j < 8; j++) {
            const int cc = n0 + wn + j * 8 + 2 * t;
            float b0 = bias[cc], b1 = bias[cc + 1];
            float x0 = fmaxf(acc[i][j][0] + b0, 0.f);
            float x1 = fmaxf(acc[i][j][1] + b1, 0.f);
            float x2 = fmaxf(acc[i][j][2] + b0, 0.f);
            float x3 = fmaxf(acc[i][j][3] + b1, 0.f);
            *(uint32_t*)(C + (long long)r0 * N + cc) =
                packh2(__float2half_rn(x0), __float2half_rn(x1));
            *(uint32_t*)(C + (long long)(r0 + 8) * N + cc) =
                packh2(__float2half_rn(x2), __float2half_rn(x3));
        }
    }
}

// ===========================================================================
// S GEMM with online-exp epilogue: e = exp(s - rowmax_tile) -> fp16 + stats
// ===========================================================================
__global__ __launch_bounds__(THREADS, 2) void gemm_qk(
    const __half* __restrict__ Q, const __half* __restrict__ Kx,
    __half* __restrict__ E, float* __restrict__ mloc, float* __restrict__ rsum)
{
    extern __shared__ char smc[];
    __shared__ float sred[2][128];
    const uint32_t sbase = smem_u32(smc);

    const int tid = threadIdx.x;
    const int wid = tid >> 5;
    const int lane = tid & 31;
    const int g = lane >> 2;
    const int t = lane & 3;
    const int bz = blockIdx.z;

    const __half* Ab = Q + ((long long)bz * NN * HH);
    const __half* Bb = Kx + ((long long)bz * NN * HH);
    const int m0 = blockIdx.y * BM;
    const int n0 = blockIdx.x * BN;
    const int wm = (wid & 3) * 32;
    const int wn = (wid >> 2) * 64;
    const int K = HH;

    float acc[2][8][4];
#pragma unroll
    for (int i = 0; i < 2; i++)
#pragma unroll
        for (int j = 0; j < 8; j++)
#pragma unroll
            for (int r = 0; r < 4; r++) acc[i][j][r] = 0.0f;

    const int niter = K / BK64;   // 8

#pragma unroll
    for (int it = 0; it < SSTAGES - 1; it++) { ISSUE64(Ab, Bb, K, it); CP_COMMIT(); }

    const int a_row = lane & 15;
    const int a_kc = (lane >> 4) * 8;
    const int b_n = ((lane >> 4) << 3) + (lane & 7);
    const int b_kc = ((lane >> 3) & 1) * 8;

    for (int it = 0; it < niter; it++) {
        CP_WAIT(SSTAGES - 2);
        __syncthreads();
        if (it + SSTAGES - 1 < niter) { ISSUE64(Ab, Bb, K, it + SSTAGES - 1); }
        CP_COMMIT();

        const uint32_t stg = sbase + (it % SSTAGES) * SSTAGE_B;
#pragma unroll
        for (int kk = 0; kk < BK64; kk += 16) {
            uint32_t Af[2][4];
#pragma unroll
            for (int i = 0; i < 2; i++)
                ldsm4(Af[i], stg + (uint32_t)(wm + i * 16 + a_row) * PITCH64
                               + (uint32_t)(kk + a_kc) * 2);
#pragma unroll
            for (int p = 0; p < 4; p++) {
                uint32_t Bf[4];
                ldsm4(Bf, stg + PLANE64 + (uint32_t)(wn + p * 16 + b_n) * PITCH64
                                        + (uint32_t)(kk + b_kc) * 2);
#pragma unroll
                for (int i = 0; i < 2; i++) {
                    mma_f16(acc[i][2 * p],     Af[i], &Bf[0]);
                    mma_f16(acc[i][2 * p + 1], Af[i], &Bf[2]);
                }
            }
        }
    }

    // ---- online-exp epilogue ----
    const int R0 = wm + g, R1 = wm + g + 8, R2 = wm + 16 + g, R3 = wm + 24 + g;
    const int half = wid >> 2;

    float rm[4] = {-1e30f, -1e30f, -1e30f, -1e30f};
#pragma unroll
    for (int j = 0; j < 8; j++) {
        rm[0] = fmaxf(rm[0], fmaxf(acc[0][j][0], acc[0][j][1]));
        rm[1] = fmaxf(rm[1], fmaxf(acc[0][j][2], acc[0][j][3]));
        rm[2] = fmaxf(rm[2], fmaxf(acc[1][j][0], acc[1][j][1]));
        rm[3] = fmaxf(rm[3], fmaxf(acc[1][j][2], acc[1][j][3]));
    }
#pragma unroll
    for (int o = 1; o <= 2; o <<= 1)
#pragma unroll
        for (int k = 0; k < 4; k++)
            rm[k] = fmaxf(rm[k], __shfl_xor_sync(0xffffffffu, rm[k], o));

    __syncthreads();
    if (t == 0) {
        sred[half][R0] = rm[0]; sred[half][R1] = rm[1];
        sred[half][R2] = rm[2]; sred[half][R3] = rm[3];
    }
    __syncthreads();
    float gm[4];
    gm[0] = fmaxf(sred[0][R0], sred[1][R0]);
    gm[1] = fmaxf(sred[0][R1], sred[1][R1]);
    gm[2] = fmaxf(sred[0][R2], sred[1][R2]);
    gm[3] = fmaxf(sred[0][R3], sred[1][R3]);
    __syncthreads();

    float rs[4] = {0.f, 0.f, 0.f, 0.f};
#pragma unroll
    for (int j = 0; j < 8; j++) {
        acc[0][j][0] = __expf(acc[0][j][0] - gm[0]);
        acc[0][j][1] = __expf(acc[0][j][1] - gm[0]);
        rs[0] += acc[0][j][0] + acc[0][j][1];
        acc[0][j][2] = __expf(acc[0][j][2] - gm[1]);
        acc[0][j][3] = __expf(acc[0][j][3] - gm[1]);
        rs[1] += acc[0][j][2] + acc[0][j][3];
        acc[1][j][0] = __expf(acc[1][j][0] - gm[2]);
        acc[1][j][1] = __expf(acc[1][j][1] - gm[2]);
        rs[2] += acc[1][j][0] + acc[1][j][1];
        acc[1][j][2] = __expf(acc[1][j][2] - gm[3]);
        acc[1][j][3] = __expf(acc[1][j][3] - gm[3]);
        rs[3] += acc[1][j][2] + acc[1][j][3];
    }
#pragma unroll
    for (int o = 1; o <= 2; o <<= 1)
#pragma unroll
        for (int k = 0; k < 4; k++)
            rs[k] += __shfl_xor_sync(0xffffffffu, rs[k], o);

    if (t == 0 && half == 0) {
        sred[0][R0] = rs[0]; sred[0][R1] = rs[1];
        sred[0][R2] = rs[2]; sred[0][R3] = rs[3];
    }
    __syncthreads();
    if (t == 0 && half == 1) {
        atomicAdd(&sred[0][R0], rs[0]); atomicAdd(&sred[0][R1], rs[1]);
        atomicAdd(&sred[0][R2], rs[2]); atomicAdd(&sred[0][R3], rs[3]);
    }
    __syncthreads();

    if (t == 0 && half == 0) {
        const long long sb = ((long long)(bz * NTILE + blockIdx.x) << 10) + m0;
        mloc[sb + R0] = gm[0]; rsum[sb + R0] = sred[0][R0];
        mloc[sb + R1] = gm[1]; rsum[sb + R1] = sred[0][R1];
        mloc[sb + R2] = gm[2]; rsum[sb + R2] = sred[0][R2];
        mloc[sb + R3] = gm[3]; rsum[sb + R3] = sred[0][R3];
    }

    __half* Eb = E + ((long long)bz << 20);
#pragma unroll
    for (int i = 0; i < 2; i++) {
        const int r0 = m0 + wm + i * 16 + g;
#pragma unroll
        for (int j = 0; j < 8; j++) {
            const int cc = n0 + wn + j * 8 + 2 * t;
            *(uint32_t*)(Eb + (long long)r0 * NN + cc) =
                packh2(__float2half_rn(acc[i][j][0]), __float2half_rn(acc[i][j][1]));
            *(uint32_t*)(Eb + (long long)(r0 + 8) * NN + cc) =
                packh2(__float2half_rn(acc[i][j][2]), __float2half_rn(acc[i][j][3]));
        }
    }
}

// ===========================================================================
// stats combine
// ===========================================================================
__global__ __launch_bounds__(256) void stats_kernel(
    const float* __restrict__ mloc, const float* __restrict__ rsum,
    float* __restrict__ scl)
{
    const int idx = blockIdx.x * blockDim.x + threadIdx.x;
    const int b = idx >> 10, r = idx & 1023;
    float m[NTILE], s[NTILE];
    float M = -1e30f;
#pragma unroll
    for (int tt = 0; tt < NTILE; tt++) {
        const long long p = ((long long)(b * NTILE + tt) << 10) + r;
        m[tt] = mloc[p]; s[tt] = rsum[p];
        M = fmaxf(M, m[tt]);
    }
    float denom = 0.f;
#pragma unroll
    for (int tt = 0; tt < NTILE; tt++) {
        m[tt] = __expf(m[tt] - M);
        denom += s[tt] * m[tt];
    }
    const float inv = 1.0f / denom;
#pragma unroll
    for (int tt = 0; tt < NTILE; tt++)
        scl[((long long)(b * NTILE + tt) << 10) + r] = m[tt] * inv;
}

// ===========================================================================
// O GEMM: O = (diag-scaled E) * Vt^T -> half-pair
// ===========================================================================
__global__ __launch_bounds__(THREADS, 2) void gemm_pv(
    const __half* __restrict__ E, const __half* __restrict__ Vt,
    const float* __restrict__ scl, __half* __restrict__ O2, long long sPC)
{
    extern __shared__ char smc[];
    __shared__ float sscl[NTILE][128];
    const uint32_t sbase = smem_u32(smc);

    const int tid = threadIdx.x;
    const int wid = tid >> 5;
    const int lane = tid & 31;
    const int g = lane >> 2;
    const int t = lane & 3;
    const int bz = blockIdx.z;

    const __half* Ab = E + ((long long)bz << 20);
    const __half* Bb = Vt + ((long long)bz * HH * NN);
    const int m0 = blockIdx.y * BM;
    const int n0 = blockIdx.x * BN;
    const int wm = (wid & 3) * 32;
    const int wn = (wid >> 2) * 64;
    const int N = HH, K = NN;

    for (int idx = tid; idx < NTILE * 128; idx += THREADS) {
        const int tt = idx >> 7, r = idx & 127;
        sscl[tt][r] = scl[((long long)(bz * NTILE + tt) << 10) + m0 + r];
    }

    float acc[2][8][4];
#pragma unroll
    for (int i = 0; i < 2; i++)
#pragma unroll
        for (int j = 0; j < 8; j++)
#pragma unroll
            for (int r = 0; r < 4; r++) acc[i][j][r] = 0.0f;

    const int niter = K / BK64;   // 16

#pragma unroll
    for (int it = 0; it < SSTAGES - 1; it++) { ISSUE64(Ab, Bb, K, it); CP_COMMIT(); }
    __syncthreads();   // sscl ready

    const int a_row = lane & 15;
    const int a_kc = (lane >> 4) * 8;
    const int b_n = ((lane >> 4) << 3) + (lane & 7);
    const int b_kc = ((lane >> 3) & 1) * 8;

    const int R0 = wm + g, R1 = wm + g + 8, R2 = wm + 16 + g, R3 = wm + 24 + g;
    __half2 hs[4];

    for (int it = 0; it < niter; it++) {
        CP_WAIT(SSTAGES - 2);
        __syncthreads();
        if (it + SSTAGES - 1 < niter) { ISSUE64(Ab, Bb, K, it + SSTAGES - 1); }
        CP_COMMIT();

        if ((it & 1) == 0) {              // key-tile = 128 keys = 2 iters of 64
            const int tt = it >> 1;
            hs[0] = __float2half2_rn(sscl[tt][R0]);
            hs[1] = __float2half2_rn(sscl[tt][R1]);
            hs[2] = __float2half2_rn(sscl[tt][R2]);
            hs[3] = __float2half2_rn(sscl[tt][R3]);
        }

        const uint32_t stg = sbase + (it % SSTAGES) * SSTAGE_B;
#pragma unroll
        for (int kk = 0; kk < BK64; kk += 16) {
            uint32_t Af[2][4];
#pragma unroll
            for (int i = 0; i < 2; i++) {
                ldsm4(Af[i], stg + (uint32_t)(wm + i * 16 + a_row) * PITCH64
                               + (uint32_t)(kk + a_kc) * 2);
                Af[i][0] = mulh2(Af[i][0], hs[2 * i]);
                Af[i][1] = mulh2(Af[i][1], hs[2 * i + 1]);
                Af[i][2] = mulh2(Af[i][2], hs[2 * i]);
                Af[i][3] = mulh2(Af[i][3], hs[2 * i + 1]);
            }
#pragma unroll
            for (int p = 0; p < 4; p++) {
                uint32_t Bf[4];
                ldsm4(Bf, stg + PLANE64 + (uint32_t)(wn + p * 16 + b_n) * PITCH64
                                        + (uint32_t)(kk + b_kc) * 2);
#pragma unroll
                for (int i = 0; i < 2; i++) {
                    mma_f16(acc[i][2 * p],     Af[i], &Bf[0]);
                    mma_f16(acc[i][2 * p + 1], Af[i], &Bf[2]);
                }
            }
        }
    }

    __half* Ch = O2 + (long long)bz * NN * HH;
    __half* Cl = Ch + sPC;
#pragma unroll
    for (int i = 0; i < 2; i++) {
        const int r0 = m0 + wm + i * 16 + g;
#pragma unroll
        for (int j = 0; j < 8; j++) {
            const int cc = n0 + wn + j * 8 + 2 * t;
            __half h0, l0, h1, l1, h2, l2, h3, l3;
            h_split(acc[i][j][0], h0, l0); h_split(acc[i][j][1], h1, l1);
            h_split(acc[i][j][2], h2, l2); h_split(acc[i][j][3], h3, l3);
            *(uint32_t*)(Ch + (long long)r0 * N + cc)       = packh2(h0, h1);
            *(uint32_t*)(Cl + (long long)r0 * N + cc)       = packh2(l0, l1);
            *(uint32_t*)(Ch + (long long)(r0 + 8) * N + cc) = packh2(h2, h3);
            *(uint32_t*)(Cl + (long long)(r0 + 8) * N + cc) = packh2(l2, l3);
        }
    }
}

// ===========================================================================
// Pair fp16 NT GEMM (3 MMAs): out = relu(o2 Wo2^T + bo), fp32 out. BK=32.
// ===========================================================================
__global__ __launch_bounds__(THREADS) void gemm_p3(
    const __half* __restrict__ A, const __half* __restrict__ B,
    const float* __restrict__ bias, float* __restrict__ C,
    int M, int N, int K, long long sPA, long long sPB)
{
    extern __shared__ char smc[];
    const uint32_t sbase = smem_u32(smc);

    const int tid = threadIdx.x;
    const int wid = tid >> 5;
    const int lane = tid & 31;
    const int g = lane >> 2;
    const int t = lane & 3;

    const __half* Ah = A;
    const __half* Al = A + sPA;
    const __half* Bh = B;
    const __half* Bl = B + sPB;
    const int m0 = blockIdx.y * BM;
    const int n0 = blockIdx.x * BN;
    const int wm = (wid & 3) * 32;
    const int wn = (wid >> 2) * 64;

    float acc[2][8][4];
#pragma unroll
    for (int i = 0; i < 2; i++)
#pragma unroll
        for (int j = 0; j < 8; j++)
#pragma unroll
            for (int r = 0; r < 4; r++) acc[i][j][r] = 0.0f;

    const int niter = K / BK32;

    auto issue_loads = [&](int it) {
        const int s = it % PSTAGES;
        const int k0 = it * BK32;
        const uint32_t stg = sbase + s * PSTAGE_B;
#pragma unroll
        for (int c = 0; c < 8; c++) {
            const int id = tid + c * 256;
            const int seg = id >> 9;
            const int rid = id & 511;
            const int row = rid >> 2, ch = rid & 3;
            const __half* src;
            int grow;
            if (seg < 2) { src = (seg == 0) ? Ah : Al; grow = m0 + row; }
            else         { src = (seg == 2) ? Bh : Bl; grow = n0 + row; }
            cp16(stg + seg * PLANE32 + row * 80 + ch * 16,
                 src + (long long)grow * K + k0 + ch * 8);
        }
    };

#pragma unroll
    for (int it = 0; it < PSTAGES - 1; it++) { issue_loads(it); CP_COMMIT(); }

    const int a_row = lane & 15;
    const int a_kc = (lane >> 4) * 8;
    const int b_n = ((lane >> 4) << 3) + (lane & 7);
    const int b_kc = ((lane >> 3) & 1) * 8;

    for (int it = 0; it < niter; it++) {
        CP_WAIT(PSTAGES - 2);
        __syncthreads();
        if (it + PSTAGES - 1 < niter) issue_loads(it + PSTAGES - 1);
        CP_COMMIT();

        const uint32_t stg = sbase + (it % PSTAGES) * PSTAGE_B;
#pragma unroll
        for (int kk = 0; kk < BK32; kk += 16) {
            uint32_t Afh[2][4], Afl[2][4];
#pragma unroll
            for (int i = 0; i < 2; i++) {
                const uint32_t ao = (uint32_t)(wm + i * 16 + a_row) * 80
                                  + (uint32_t)(kk + a_kc) * 2;
                ldsm4(Afh[i], stg + ao);
                ldsm4(Afl[i], stg + PLANE32 + ao);
            }
#pragma unroll
            for (int p = 0; p < 4; p++) {
                uint32_t Bfh[4], Bfl[4];
                const uint32_t bo = (uint32_t)(wn + p * 16 + b_n) * 80
                                  + (uint32_t)(kk + b_kc) * 2;
                ldsm4(Bfh, stg + 2 * PLANE32 + bo);
                ldsm4(Bfl, stg + 3 * PLANE32 + bo);
#pragma unroll
                for (int i = 0; i < 2; i++) {
                    mma_f16(acc[i][2 * p],     Afh[i], &Bfh[0]);
                    mma_f16(acc[i][2 * p],     Afl[i], &Bfh[0]);
                    mma_f16(acc[i][2 * p],     Afh[i], &Bfl[0]);
                    mma_f16(acc[i][2 * p + 1], Afh[i], &Bfh[2]);
                    mma_f16(acc[i][2 * p + 1], Afl[i], &Bfh[2]);
                    mma_f16(acc[i][2 * p + 1], Afh[i], &Bfl[2]);
                }
            }
        }
    }

#pragma unroll
    for (int i = 0; i < 2; i++) {
        const int r0 = m0 + wm + i * 16 + g;
#pragma unroll
        for (int j = 0; j < 8; j++) {
            const int cc = n0 + wn + j * 8 + 2 * t;
            float b0 = bias[cc], b1 = bias[cc + 1];
            *(float2*)(C + (long long)r0 * N + cc) =
                make_float2(fmaxf(acc[i][j][0] + b0, 0.f), fmaxf(acc[i][j][1] + b1, 0.f));
            *(float2*)(C + (long long)(r0 + 8) * N + cc) =
                make_float2(fmaxf(acc[i][j][2] + b0, 0.f), fmaxf(acc[i][j][3] + b1, 0.f));
        }
    }
}

// ---------------------------------------------------------------------------
// fused pack: h->h16, Wq/Wk/Wv->fp16, Wo->pair
// ---------------------------------------------------------------------------
#define PK_H (HB_ELEMS / 4)
#define PK_W (W1_ELEMS / 4)
__global__ __launch_bounds__(256) void pack_all(
    const float* __restrict__ h, const float* __restrict__ Wq,
    const float* __restrict__ Wk, const float* __restrict__ Wv,
    const float* __restrict__ Wo,
    __half* __restrict__ h16, __half* __restrict__ wq16,
    __half* __restrict__ wk16, __half* __restrict__ wv16,
    __half* __restrict__ wo2)
{
    const int total = PK_H + 4 * PK_W;
    for (int i = blockIdx.x * blockDim.x + threadIdx.x; i < total;
         i += gridDim.x * blockDim.x) {
        if (i < PK_H + 3 * PK_W) {
            const float* src; __half* dst; int idx;
            if (i < PK_H) { src = h; dst = h16; idx = i; }
            else {
                int r = i - PK_H;
                int seg = r / PK_W; idx = r % PK_W;
                src = (seg == 0) ? Wq : (seg == 1) ? Wk : Wv;
                dst = (seg == 0) ? wq16 : (seg == 1) ? wk16 : wv16;
            }
            float4 v = ((const float4*)src)[idx];
            ((uint2*)dst)[idx] = make_uint2(
                packh2(__float2half_rn(v.x), __float2half_rn(v.y)),
                packh2(__float2half_rn(v.z), __float2half_rn(v.w)));
        } else {
            int idx = i - PK_H - 3 * PK_W;
            float4 v = ((const float4*)Wo)[idx];
            __half h0, l0, h1, l1, h2, l2, h3, l3;
            h_split(v.x, h0, l0); h_split(v.y, h1, l1);
            h_split(v.z, h2, l2); h_split(v.w, h3, l3);
            ((uint2*)wo2)[idx] = make_uint2(packh2(h0, h1), packh2(h2, h3));
            ((uint2*)(wo2 + 2 * W1_ELEMS))[idx] = make_uint2(packh2(l0, l1), packh2(l2, l3));
        }
    }
}

// ---------------------------------------------------------------------------
// transpose fp16 v[b][n][h] -> vt[b][h][n]
// ---------------------------------------------------------------------------
__global__ __launch_bounds__(256) void transpose_kernel(
    const __half* __restrict__ v, __half* __restrict__ vt)
{
    __shared__ __half tile[32][34];
    const int b = blockIdx.z;
    const int h0 = blockIdx.x * 32;
    const int n0 = blockIdx.y * 32;
    const int tx = threadIdx.x & 31;
    const int ty = threadIdx.x >> 5;

    const __half* vb = v + (long long)b * NN * HH;
    __half* vtb = vt + (long long)b * HH * NN;

#pragma unroll
    for (int j = 0; j < 32; j += 8)
        tile[ty + j][tx] = vb[(long long)(n0 + ty + j) * HH + h0 + tx];
    __syncthreads();
#pragma unroll
    for (int j = 0; j < 32; j += 8)
        vtb[(long long)(h0 + ty + j) * NN + n0 + tx] = tile[tx][ty + j];
}

// ---------------------------------------------------------------------------
// kernel_launch — inputs: h, Wv, bv, Wk, bk, Wq, bq, Wo, bo
// ---------------------------------------------------------------------------
extern "C" void kernel_launch(void* const* d_in, const int* in_sizes, int n_in,
                              void* d_out, int out_size)
{
    const float* h  = (const float*)d_in[0];
    const float* Wv = (const float*)d_in[1];
    const float* bv = (const float*)d_in[2];
    const float* Wk = (const float*)d_in[3];
    const float* bk = (const float*)d_in[4];
    const float* Wq = (const float*)d_in[5];
    const float* bq = (const float*)d_in[6];
    const float* Wo = (const float*)d_in[7];
    const float* bo = (const float*)d_in[8];
    float* out = (float*)d_out;

    __half *h16, *wq16, *wk16, *wv16, *wo2, *q, *k, *v, *vt, *e, *o2;
    float *mloc, *rsum, *scl;
    cudaGetSymbolAddress((void**)&h16,  g_h16);
    cudaGetSymbolAddress((void**)&wq16, g_wq16);
    cudaGetSymbolAddress((void**)&wk16, g_wk16);
    cudaGetSymbolAddress((void**)&wv16, g_wv16);
    cudaGetSymbolAddress((void**)&wo2,  g_wo2);
    cudaGetSymbolAddress((void**)&q,    g_q);
    cudaGetSymbolAddress((void**)&k,    g_k);
    cudaGetSymbolAddress((void**)&v,    g_v);
    cudaGetSymbolAddress((void**)&vt,   g_vt);
    cudaGetSymbolAddress((void**)&e,    g_e);
    cudaGetSymbolAddress((void**)&mloc, g_mloc);
    cudaGetSymbolAddress((void**)&rsum, g_rsum);
    cudaGetSymbolAddress((void**)&scl,  g_scl);
    cudaGetSymbolAddress((void**)&o2,   g_o2);

    cudaFuncSetAttribute(gemm_proj, cudaFuncAttributeMaxDynamicSharedMemorySize, SSMEM);
    cudaFuncSetAttribute(gemm_qk,   cudaFuncAttributeMaxDynamicSharedMemorySize, SSMEM);
    cudaFuncSetAttribute(gemm_pv,   cudaFuncAttributeMaxDynamicSharedMemorySize, SSMEM);
    cudaFuncSetAttribute(gemm_p3,   cudaFuncAttributeMaxDynamicSharedMemorySize, PSMEM);

    const int M = BB * NN;   // 32768

    // 1. fused pack
    pack_all<<<2048, 256>>>(h, Wq, Wk, Wv, Wo, h16, wq16, wk16, wv16, wo2);

    // 2. fused Q/K/V projections (grid.z selects which)
    {
        dim3 grid(HH / BN, M / BM, 3);
        gemm_proj<<<grid, THREADS, SSMEM>>>(h16, wq16, wk16, wv16,
                                            bq, bk, bv, q, k, v);
    }

    // 3. vt[b][h][n] = v[b][n][h]
    {
        dim3 grid(HH / 32, NN / 32, BB);
        transpose_kernel<<<grid, 256>>>(v, vt);
    }

    // 4. S GEMM + online exp -> e fp16 + per-tile stats
    {
        dim3 grid(NN / BN, NN / BM, BB);
        gemm_qk<<<grid, THREADS, SSMEM>>>(q, k, e, mloc, rsum);
    }

    // 5. stats combine -> scales
    stats_kernel<<<M / 256, 256>>>(mloc, rsum, scl);

    // 6. O = scaled-E * Vt^T -> fp16 pair
    {
        dim3 grid(HH / BN, NN / BM, BB);
        gemm_pv<<<grid, THREADS, SSMEM>>>(e, vt, scl, o2, QKV_ELEMS);
    }

    // 7. out = relu(O Wo^T + bo) -> fp32
    {
        dim3 grid(DD / BN, M / BM, 1);
        gemm_p3<<<grid, THREADS, PSMEM>>>(o2, wo2, bo, out, M, DD, HH,
                                          QKV_ELEMS, W1_ELEMS);
    }
}

// round 9
// speedup vs baseline: 5.6460x; 1.0315x over previous
#include <cuda_runtime.h>
#include <cuda_fp16.h>
#include <cstdint>

// Problem dims
#define BB 32
#define NN 1024
#define DD 256
#define HH 512
#define HB_ELEMS (BB * NN * DD)
#define QKV_ELEMS (BB * NN * HH)
#define S_ELEMS ((long long)BB * NN * NN)
#define W1_ELEMS (HH * DD)
#define NTILE 8                          // 1024 keys / 128 per S col-tile

// ---------------- scratch ----------------
__device__ __half g_h16[HB_ELEMS];
__device__ __half g_wq16[W1_ELEMS], g_wk16[W1_ELEMS], g_wv16[W1_ELEMS];
__device__ __half g_wo2[2 * W1_ELEMS];          // pair: hi, lo planes
__device__ __half g_q[QKV_ELEMS], g_k[QKV_ELEMS];
__device__ __half g_vt[QKV_ELEMS];              // [b][h][n]
__device__ __half g_e[S_ELEMS];                 // exp(s - m_tile), fp16
__device__ float  g_mloc[BB * NTILE * NN];
__device__ float  g_rsum[BB * NTILE * NN];
__device__ __half g_o2[2 * QKV_ELEMS];          // o pair

// ---------------- helpers ----------------
__device__ __forceinline__ void h_split(float x, __half& h, __half& l) {
    h = __float2half_rn(x);
    l = __float2half_rn(x - __half2float(h));
}
__device__ __forceinline__ uint32_t packh2(__half a, __half b) {
    __half2 t = __halves2half2(a, b);
    return *reinterpret_cast<uint32_t*>(&t);
}
__device__ __forceinline__ uint32_t mulh2(uint32_t a, __half2 s) {
    __half2 x = *reinterpret_cast<__half2*>(&a);
    x = __hmul2(x, s);
    return *reinterpret_cast<uint32_t*>(&x);
}
__device__ __forceinline__ uint32_t smem_u32(const void* p) {
    uint32_t a;
    asm("{ .reg .u64 t; cvta.to.shared.u64 t, %1; cvt.u32.u64 %0, t; }" : "=r"(a) : "l"(p));
    return a;
}
__device__ __forceinline__ void cp16(uint32_t dst, const void* src) {
    asm volatile("cp.async.cg.shared.global [%0], [%1], 16;" :: "r"(dst), "l"(src));
}
#define CP_COMMIT() asm volatile("cp.async.commit_group;" ::: "memory")
#define CP_WAIT(n)  asm volatile("cp.async.wait_group %0;" :: "n"(n) : "memory")

__device__ __forceinline__ void ldsm4(uint32_t* r, uint32_t addr) {
    asm volatile("ldmatrix.sync.aligned.m8n8.x4.shared.b16 {%0,%1,%2,%3}, [%4];"
        : "=r"(r[0]), "=r"(r[1]), "=r"(r[2]), "=r"(r[3]) : "r"(addr));
}
__device__ __forceinline__ void mma_f16(float* d, const uint32_t* a, const uint32_t* b) {
    asm volatile(
        "mma.sync.aligned.m16n8k16.row.col.f32.f16.f16.f32 "
        "{%0,%1,%2,%3}, {%4,%5,%6,%7}, {%8,%9}, {%0,%1,%2,%3};"
        : "+f"(d[0]), "+f"(d[1]), "+f"(d[2]), "+f"(d[3])
        : "r"(a[0]), "r"(a[1]), "r"(a[2]), "r"(a[3]), "r"(b[0]), "r"(b[1]));
}

// ---------------- tile config ----------------
#define BM 128
#define BN 128
#define THREADS 256

// single-plane GEMMs: BK=64, pitch 144 B, 3 stages, 2 CTAs/SM
#define BK64 64
#define PITCH64 144
#define PLANE64 (128 * PITCH64)          // 18432 B
#define SSTAGES 3
#define SSTAGE_B (2 * PLANE64)           // 36864
#define SSMEM (SSTAGES * SSTAGE_B)       // 110592

// pair GEMM (out-proj): BK=32, pitch 80 B, 3 stages
#define BK32 32
#define PLANE32 (128 * 80)
#define PSTAGES 3
#define PSTAGE_B (4 * PLANE32)
#define PSMEM (PSTAGES * PSTAGE_B)       // 122880

// transposed-epilogue staging pitch (halves)
#define PT 132

// ---- shared mainloop load macro (BK=64 single-plane) ----
#define ISSUE64(Ab, Bb, Kdim, it)                                              \
    do {                                                                       \
        const int s_ = (it) % SSTAGES;                                         \
        const int k0_ = (it) * BK64;                                           \
        const uint32_t stg_ = sbase + s_ * SSTAGE_B;                           \
        _Pragma("unroll")                                                      \
        for (int c_ = 0; c_ < 8; c_++) {                                       \
            const int id_ = tid + c_ * 256;                                    \
            const int seg_ = id_ >> 10;                                        \
            const int rid_ = id_ & 1023;                                       \
            const int row_ = rid_ >> 3, ch_ = rid_ & 7;                        \
            const __half* src_ = seg_ ? (Bb + (long long)(n0 + row_) * Kdim)   \
                                      : (Ab + (long long)(m0 + row_) * Kdim);  \
            cp16(stg_ + seg_ * PLANE64 + row_ * PITCH64 + ch_ * 16,            \
                 src_ + k0_ + ch_ * 8);                                        \
        }                                                                      \
    } while (0)

// ===========================================================================
// Fused Q/K/V projection: grid.z selects (W, bias, dst).
// z==2 (V): writes vt[b][h][n] directly via smem-staged transpose.
// ===========================================================================
__global__ __launch_bounds__(THREADS, 2) void gemm_proj(
    const __half* __restrict__ Hm,
    const __half* __restrict__ Wqp, const __half* __restrict__ Wkp,
    const __half* __restrict__ Wvp,
    const float* __restrict__ bqp, const float* __restrict__ bkp,
    const float* __restrict__ bvp,
    __half* __restrict__ Qp, __half* __restrict__ Kp, __half* __restrict__ Vtp)
{
    extern __shared__ char smc[];
    const uint32_t sbase = smem_u32(smc);

    const int tid = threadIdx.x;
    const int wid = tid >> 5;
    const int lane = tid & 31;
    const int g = lane >> 2;
    const int t = lane & 3;
    const int z = blockIdx.z;

    const __half* Ab = Hm;
    const __half* Bb = (z == 0) ? Wqp : (z == 1) ? Wkp : Wvp;
    const float* bias = (z == 0) ? bqp : (z == 1) ? bkp : bvp;

    const int m0 = blockIdx.y * BM;
    const int n0 = blockIdx.x * BN;
    const int wm = (wid & 3) * 32;
    const int wn = (wid >> 2) * 64;
    const int K = DD, N = HH;

    float acc[2][8][4];
#pragma unroll
    for (int i = 0; i < 2; i++)
#pragma unroll
        for (int j = 0; j < 8; j++)
#pragma unroll
            for (int r = 0; r < 4; r++) acc[i][j][r] = 0.0f;

    const int niter = K / BK64;     // 4

#pragma unroll
    for (int it = 0; it < SSTAGES - 1; it++) { ISSUE64(Ab, Bb, K, it); CP_COMMIT(); }

    const int a_row = lane & 15;
    const int a_kc = (lane >> 4) * 8;
    const int b_n = ((lane >> 4) << 3) + (lane & 7);
    const int b_kc = ((lane >> 3) & 1) * 8;

    for (int it = 0; it < niter; it++) {
        CP_WAIT(SSTAGES - 2);
        __syncthreads();
        if (it + SSTAGES - 1 < niter) { ISSUE64(Ab, Bb, K, it + SSTAGES - 1); }
        CP_COMMIT();

        const uint32_t stg = sbase + (it % SSTAGES) * SSTAGE_B;
#pragma unroll
        for (int kk = 0; kk < BK64; kk += 16) {
            uint32_t Af[2][4];
#pragma unroll
            for (int i = 0; i < 2; i++)
                ldsm4(Af[i], stg + (uint32_t)(wm + i * 16 + a_row) * PITCH64
                               + (uint32_t)(kk + a_kc) * 2);
#pragma unroll
            for (int p = 0; p < 4; p++) {
                uint32_t Bf[4];
                ldsm4(Bf, stg + PLANE64 + (uint32_t)(wn + p * 16 + b_n) * PITCH64
                                        + (uint32_t)(kk + b_kc) * 2);
#pragma unroll
                for (int i = 0; i < 2; i++) {
                    mma_f16(acc[i][2 * p],     Af[i], &Bf[0]);
                    mma_f16(acc[i][2 * p + 1], Af[i], &Bf[2]);
                }
            }
        }
    }

    if (z < 2) {
        __half* C = (z == 0) ? Qp : Kp;
#pragma unroll
        for (int i = 0; i < 2; i++) {
            const int r0 = m0 + wm + i * 16 + g;
#pragma unroll
            for (int j = 0; j < 8; j++) {
                const int cc = n0 + wn + j * 8 + 2 * t;
                float b0 = bias[cc], b1 = bias[cc + 1];
                float x0 = fmaxf(acc[i][j][0] + b0, 0.f);
                float x1 = fmaxf(acc[i][j][1] + b1, 0.f);
                float x2 = fmaxf(acc[i][j][2] + b0, 0.f);
                float x3 = fmaxf(acc[i][j][3] + b1, 0.f);
                *(uint32_t*)(C + (long long)r0 * N + cc) =
                    packh2(__float2half_rn(x0), __float2half_rn(x1));
                *(uint32_t*)(C + (long long)(r0 + 8) * N + cc) =
                    packh2(__float2half_rn(x2), __float2half_rn(x3));
            }
        }
    } else {
        // V: stage tile in smem, write transposed vt[b][h][n]
        __syncthreads();                        // done with stage buffers
        __half* tile = (__half*)smc;            // reuse: 128 x PT halves
#pragma unroll
        for (int i = 0; i < 2; i++) {
            const int rl0 = wm + i * 16 + g;    // local row 0..127
#pragma unroll
            for (int j = 0; j < 8; j++) {
                const int cl = wn + j * 8 + 2 * t;   // local col
                float b0 = bias[n0 + cl], b1 = bias[n0 + cl + 1];
                tile[rl0 * PT + cl]           = __float2half_rn(fmaxf(acc[i][j][0] + b0, 0.f));
                tile[rl0 * PT + cl + 1]       = __float2half_rn(fmaxf(acc[i][j][1] + b1, 0.f));
                tile[(rl0 + 8) * PT + cl]     = __float2half_rn(fmaxf(acc[i][j][2] + b0, 0.f));
                tile[(rl0 + 8) * PT + cl + 1] = __float2half_rn(fmaxf(acc[i][j][3] + b1, 0.f));
            }
        }
        __syncthreads();
        const int b = m0 >> 10;
        const int nloc = m0 & 1023;
        __half* vtb = Vtp + (long long)b * HH * NN + nloc;
        const int g2 = tid >> 7;               // 0/1
        const int l128 = tid & 127;            // token within tile
#pragma unroll
        for (int jc = 0; jc < 64; jc++) {
            const int c = g2 * 64 + jc;
            vtb[(long long)(n0 + c) * NN + l128] = tile[l128 * PT + c];
        }
    }
}

// ===========================================================================
// S GEMM with online-exp epilogue: e = exp(s - rowmax_tile) -> fp16 + stats
// ===========================================================================
__global__ __launch_bounds__(THREADS, 2) void gemm_qk(
    const __half* __restrict__ Q, const __half* __restrict__ Kx,
    __half* __restrict__ E, float* __restrict__ mloc, float* __restrict__ rsum)
{
    extern __shared__ char smc[];
    __shared__ float sred[2][128];
    const uint32_t sbase = smem_u32(smc);

    const int tid = threadIdx.x;
    const int wid = tid >> 5;
    const int lane = tid & 31;
    const int g = lane >> 2;
    const int t = lane & 3;
    const int bz = blockIdx.z;

    const __half* Ab = Q + ((long long)bz * NN * HH);
    const __half* Bb = Kx + ((long long)bz * NN * HH);
    const int m0 = blockIdx.y * BM;
    const int n0 = blockIdx.x * BN;
    const int wm = (wid & 3) * 32;
    const int wn = (wid >> 2) * 64;
    const int K = HH;

    float acc[2][8][4];
#pragma unroll
    for (int i = 0; i < 2; i++)
#pragma unroll
        for (int j = 0; j < 8; j++)
#pragma unroll
            for (int r = 0; r < 4; r++) acc[i][j][r] = 0.0f;

    const int niter = K / BK64;   // 8

#pragma unroll
    for (int it = 0; it < SSTAGES - 1; it++) { ISSUE64(Ab, Bb, K, it); CP_COMMIT(); }

    const int a_row = lane & 15;
    const int a_kc = (lane >> 4) * 8;
    const int b_n = ((lane >> 4) << 3) + (lane & 7);
    const int b_kc = ((lane >> 3) & 1) * 8;

    for (int it = 0; it < niter; it++) {
        CP_WAIT(SSTAGES - 2);
        __syncthreads();
        if (it + SSTAGES - 1 < niter) { ISSUE64(Ab, Bb, K, it + SSTAGES - 1); }
        CP_COMMIT();

        const uint32_t stg = sbase + (it % SSTAGES) * SSTAGE_B;
#pragma unroll
        for (int kk = 0; kk < BK64; kk += 16) {
            uint32_t Af[2][4];
#pragma unroll
            for (int i = 0; i < 2; i++)
                ldsm4(Af[i], stg + (uint32_t)(wm + i * 16 + a_row) * PITCH64
                               + (uint32_t)(kk + a_kc) * 2);
#pragma unroll
            for (int p = 0; p < 4; p++) {
                uint32_t Bf[4];
                ldsm4(Bf, stg + PLANE64 + (uint32_t)(wn + p * 16 + b_n) * PITCH64
                                        + (uint32_t)(kk + b_kc) * 2);
#pragma unroll
                for (int i = 0; i < 2; i++) {
                    mma_f16(acc[i][2 * p],     Af[i], &Bf[0]);
                    mma_f16(acc[i][2 * p + 1], Af[i], &Bf[2]);
                }
            }
        }
    }

    // ---- online-exp epilogue ----
    const int R0 = wm + g, R1 = wm + g + 8, R2 = wm + 16 + g, R3 = wm + 24 + g;
    const int half = wid >> 2;

    float rm[4] = {-1e30f, -1e30f, -1e30f, -1e30f};
#pragma unroll
    for (int j = 0; j < 8; j++) {
        rm[0] = fmaxf(rm[0], fmaxf(acc[0][j][0], acc[0][j][1]));
        rm[1] = fmaxf(rm[1], fmaxf(acc[0][j][2], acc[0][j][3]));
        rm[2] = fmaxf(rm[2], fmaxf(acc[1][j][0], acc[1][j][1]));
        rm[3] = fmaxf(rm[3], fmaxf(acc[1][j][2], acc[1][j][3]));
    }
#pragma unroll
    for (int o = 1; o <= 2; o <<= 1)
#pragma unroll
        for (int k = 0; k < 4; k++)
            rm[k] = fmaxf(rm[k], __shfl_xor_sync(0xffffffffu, rm[k], o));

    __syncthreads();
    if (t == 0) {
        sred[half][R0] = rm[0]; sred[half][R1] = rm[1];
        sred[half][R2] = rm[2]; sred[half][R3] = rm[3];
    }
    __syncthreads();
    float gm[4];
    gm[0] = fmaxf(sred[0][R0], sred[1][R0]);
    gm[1] = fmaxf(sred[0][R1], sred[1][R1]);
    gm[2] = fmaxf(sred[0][R2], sred[1][R2]);
    gm[3] = fmaxf(sred[0][R3], sred[1][R3]);
    __syncthreads();

    float rs[4] = {0.f, 0.f, 0.f, 0.f};
#pragma unroll
    for (int j = 0; j < 8; j++) {
        acc[0][j][0] = __expf(acc[0][j][0] - gm[0]);
        acc[0][j][1] = __expf(acc[0][j][1] - gm[0]);
        rs[0] += acc[0][j][0] + acc[0][j][1];
        acc[0][j][2] = __expf(acc[0][j][2] - gm[1]);
        acc[0][j][3] = __expf(acc[0][j][3] - gm[1]);
        rs[1] += acc[0][j][2] + acc[0][j][3];
        acc[1][j][0] = __expf(acc[1][j][0] - gm[2]);
        acc[1][j][1] = __expf(acc[1][j][1] - gm[2]);
        rs[2] += acc[1][j][0] + acc[1][j][1];
        acc[1][j][2] = __expf(acc[1][j][2] - gm[3]);
        acc[1][j][3] = __expf(acc[1][j][3] - gm[3]);
        rs[3] += acc[1][j][2] + acc[1][j][3];
    }
#pragma unroll
    for (int o = 1; o <= 2; o <<= 1)
#pragma unroll
        for (int k = 0; k < 4; k++)
            rs[k] += __shfl_xor_sync(0xffffffffu, rs[k], o);

    if (t == 0 && half == 0) {
        sred[0][R0] = rs[0]; sred[0][R1] = rs[1];
        sred[0][R2] = rs[2]; sred[0][R3] = rs[3];
    }
    __syncthreads();
    if (t == 0 && half == 1) {
        atomicAdd(&sred[0][R0], rs[0]); atomicAdd(&sred[0][R1], rs[1]);
        atomicAdd(&sred[0][R2], rs[2]); atomicAdd(&sred[0][R3], rs[3]);
    }
    __syncthreads();

    if (t == 0 && half == 0) {
        const long long sb = ((long long)(bz * NTILE + blockIdx.x) << 10) + m0;
        mloc[sb + R0] = gm[0]; rsum[sb + R0] = sred[0][R0];
        mloc[sb + R1] = gm[1]; rsum[sb + R1] = sred[0][R1];
        mloc[sb + R2] = gm[2]; rsum[sb + R2] = sred[0][R2];
        mloc[sb + R3] = gm[3]; rsum[sb + R3] = sred[0][R3];
    }

    __half* Eb = E + ((long long)bz << 20);
#pragma unroll
    for (int i = 0; i < 2; i++) {
        const int r0 = m0 + wm + i * 16 + g;
#pragma unroll
        for (int j = 0; j < 8; j++) {
            const int cc = n0 + wn + j * 8 + 2 * t;
            *(uint32_t*)(Eb + (long long)r0 * NN + cc) =
                packh2(__float2half_rn(acc[i][j][0]), __float2half_rn(acc[i][j][1]));
            *(uint32_t*)(Eb + (long long)(r0 + 8) * NN + cc) =
                packh2(__float2half_rn(acc[i][j][2]), __float2half_rn(acc[i][j][3]));
        }
    }
}

// ===========================================================================
// O GEMM: O = (diag-scaled E) * Vt^T -> half-pair. Scales computed inline
// from mloc/rsum with the exact same op order as the old stats kernel.
// ===========================================================================
__global__ __launch_bounds__(THREADS, 2) void gemm_pv(
    const __half* __restrict__ E, const __half* __restrict__ Vt,
    const float* __restrict__ mloc, const float* __restrict__ rsum,
    __half* __restrict__ O2, long long sPC)
{
    extern __shared__ char smc[];
    __shared__ float sscl[NTILE][128];
    const uint32_t sbase = smem_u32(smc);

    const int tid = threadIdx.x;
    const int wid = tid >> 5;
    const int lane = tid & 31;
    const int g = lane >> 2;
    const int t = lane & 3;
    const int bz = blockIdx.z;

    const __half* Ab = E + ((long long)bz << 20);
    const __half* Bb = Vt + ((long long)bz * HH * NN);
    const int m0 = blockIdx.y * BM;
    const int n0 = blockIdx.x * BN;
    const int wm = (wid & 3) * 32;
    const int wn = (wid >> 2) * 64;
    const int N = HH, K = NN;

    // inline stats: 128 rows handled by threads 0..127
    if (tid < 128) {
        const int r = m0 + tid;
        float m[NTILE], s[NTILE];
        float M = -1e30f;
#pragma unroll
        for (int tt = 0; tt < NTILE; tt++) {
            const long long p = ((long long)(bz * NTILE + tt) << 10) + r;
            m[tt] = mloc[p]; s[tt] = rsum[p];
            M = fmaxf(M, m[tt]);
        }
        float denom = 0.f;
#pragma unroll
        for (int tt = 0; tt < NTILE; tt++) {
            m[tt] = __expf(m[tt] - M);
            denom += s[tt] * m[tt];
        }
        const float inv = 1.0f / denom;
#pragma unroll
        for (int tt = 0; tt < NTILE; tt++)
            sscl[tt][tid] = m[tt] * inv;
    }

    float acc[2][8][4];
#pragma unroll
    for (int i = 0; i < 2; i++)
#pragma unroll
        for (int j = 0; j < 8; j++)
#pragma unroll
            for (int r = 0; r < 4; r++) acc[i][j][r] = 0.0f;

    const int niter = K / BK64;   // 16

#pragma unroll
    for (int it = 0; it < SSTAGES - 1; it++) { ISSUE64(Ab, Bb, K, it); CP_COMMIT(); }
    __syncthreads();   // sscl ready

    const int a_row = lane & 15;
    const int a_kc = (lane >> 4) * 8;
    const int b_n = ((lane >> 4) << 3) + (lane & 7);
    const int b_kc = ((lane >> 3) & 1) * 8;

    const int R0 = wm + g, R1 = wm + g + 8, R2 = wm + 16 + g, R3 = wm + 24 + g;
    __half2 hs[4];

    for (int it = 0; it < niter; it++) {
        CP_WAIT(SSTAGES - 2);
        __syncthreads();
        if (it + SSTAGES - 1 < niter) { ISSUE64(Ab, Bb, K, it + SSTAGES - 1); }
        CP_COMMIT();

        if ((it & 1) == 0) {              // key-tile = 128 keys = 2 iters of 64
            const int tt = it >> 1;
            hs[0] = __float2half2_rn(sscl[tt][R0]);
            hs[1] = __float2half2_rn(sscl[tt][R1]);
            hs[2] = __float2half2_rn(sscl[tt][R2]);
            hs[3] = __float2half2_rn(sscl[tt][R3]);
        }

        const uint32_t stg = sbase + (it % SSTAGES) * SSTAGE_B;
#pragma unroll
        for (int kk = 0; kk < BK64; kk += 16) {
            uint32_t Af[2][4];
#pragma unroll
            for (int i = 0; i < 2; i++) {
                ldsm4(Af[i], stg + (uint32_t)(wm + i * 16 + a_row) * PITCH64
                               + (uint32_t)(kk + a_kc) * 2);
                Af[i][0] = mulh2(Af[i][0], hs[2 * i]);
                Af[i][1] = mulh2(Af[i][1], hs[2 * i + 1]);
                Af[i][2] = mulh2(Af[i][2], hs[2 * i]);
                Af[i][3] = mulh2(Af[i][3], hs[2 * i + 1]);
            }
#pragma unroll
            for (int p = 0; p < 4; p++) {
                uint32_t Bf[4];
                ldsm4(Bf, stg + PLANE64 + (uint32_t)(wn + p * 16 + b_n) * PITCH64
                                        + (uint32_t)(kk + b_kc) * 2);
#pragma unroll
                for (int i = 0; i < 2; i++) {
                    mma_f16(acc[i][2 * p],     Af[i], &Bf[0]);
                    mma_f16(acc[i][2 * p + 1], Af[i], &Bf[2]);
                }
            }
        }
    }

    __half* Ch = O2 + (long long)bz * NN * HH;
    __half* Cl = Ch + sPC;
#pragma unroll
    for (int i = 0; i < 2; i++) {
        const int r0 = m0 + wm + i * 16 + g;
#pragma unroll
        for (int j = 0; j < 8; j++) {
            const int cc = n0 + wn + j * 8 + 2 * t;
            __half h0, l0, h1, l1, h2, l2, h3, l3;
            h_split(acc[i][j][0], h0, l0); h_split(acc[i][j][1], h1, l1);
            h_split(acc[i][j][2], h2, l2); h_split(acc[i][j][3], h3, l3);
            *(uint32_t*)(Ch + (long long)r0 * N + cc)       = packh2(h0, h1);
            *(uint32_t*)(Cl + (long long)r0 * N + cc)       = packh2(l0, l1);
            *(uint32_t*)(Ch + (long long)(r0 + 8) * N + cc) = packh2(h2, h3);
            *(uint32_t*)(Cl + (long long)(r0 + 8) * N + cc) = packh2(l2, l3);
        }
    }
}

// ===========================================================================
// Pair fp16 NT GEMM (3 MMAs): out = relu(o2 Wo2^T + bo), fp32 out. BK=32.
// ===========================================================================
__global__ __launch_bounds__(THREADS) void gemm_p3(
    const __half* __restrict__ A, const __half* __restrict__ B,
    const float* __restrict__ bias, float* __restrict__ C,
    int M, int N, int K, long long sPA, long long sPB)
{
    extern __shared__ char smc[];
    const uint32_t sbase = smem_u32(smc);

    const int tid = threadIdx.x;
    const int wid = tid >> 5;
    const int lane = tid & 31;
    const int g = lane >> 2;
    const int t = lane & 3;

    const __half* Ah = A;
    const __half* Al = A + sPA;
    const __half* Bh = B;
    const __half* Bl = B + sPB;
    const int m0 = blockIdx.y * BM;
    const int n0 = blockIdx.x * BN;
    const int wm = (wid & 3) * 32;
    const int wn = (wid >> 2) * 64;

    float acc[2][8][4];
#pragma unroll
    for (int i = 0; i < 2; i++)
#pragma unroll
        for (int j = 0; j < 8; j++)
#pragma unroll
            for (int r = 0; r < 4; r++) acc[i][j][r] = 0.0f;

    const int niter = K / BK32;

    auto issue_loads = [&](int it) {
        const int s = it % PSTAGES;
        const int k0 = it * BK32;
        const uint32_t stg = sbase + s * PSTAGE_B;
#pragma unroll
        for (int c = 0; c < 8; c++) {
            const int id = tid + c * 256;
            const int seg = id >> 9;
            const int rid = id & 511;
            const int row = rid >> 2, ch = rid & 3;
            const __half* src;
            int grow;
            if (seg < 2) { src = (seg == 0) ? Ah : Al; grow = m0 + row; }
            else         { src = (seg == 2) ? Bh : Bl; grow = n0 + row; }
            cp16(stg + seg * PLANE32 + row * 80 + ch * 16,
                 src + (long long)grow * K + k0 + ch * 8);
        }
    };

#pragma unroll
    for (int it = 0; it < PSTAGES - 1; it++) { issue_loads(it); CP_COMMIT(); }

    const int a_row = lane & 15;
    const int a_kc = (lane >> 4) * 8;
    const int b_n = ((lane >> 4) << 3) + (lane & 7);
    const int b_kc = ((lane >> 3) & 1) * 8;

    for (int it = 0; it < niter; it++) {
        CP_WAIT(PSTAGES - 2);
        __syncthreads();
        if (it + PSTAGES - 1 < niter) issue_loads(it + PSTAGES - 1);
        CP_COMMIT();

        const uint32_t stg = sbase + (it % PSTAGES) * PSTAGE_B;
#pragma unroll
        for (int kk = 0; kk < BK32; kk += 16) {
            uint32_t Afh[2][4], Afl[2][4];
#pragma unroll
            for (int i = 0; i < 2; i++) {
                const uint32_t ao = (uint32_t)(wm + i * 16 + a_row) * 80
                                  + (uint32_t)(kk + a_kc) * 2;
                ldsm4(Afh[i], stg + ao);
                ldsm4(Afl[i], stg + PLANE32 + ao);
            }
#pragma unroll
            for (int p = 0; p < 4; p++) {
                uint32_t Bfh[4], Bfl[4];
                const uint32_t bo = (uint32_t)(wn + p * 16 + b_n) * 80
                                  + (uint32_t)(kk + b_kc) * 2;
                ldsm4(Bfh, stg + 2 * PLANE32 + bo);
                ldsm4(Bfl, stg + 3 * PLANE32 + bo);
#pragma unroll
                for (int i = 0; i < 2; i++) {
                    mma_f16(acc[i][2 * p],     Afh[i], &Bfh[0]);
                    mma_f16(acc[i][2 * p],     Afl[i], &Bfh[0]);
                    mma_f16(acc[i][2 * p],     Afh[i], &Bfl[0]);
                    mma_f16(acc[i][2 * p + 1], Afh[i], &Bfh[2]);
                    mma_f16(acc[i][2 * p + 1], Afl[i], &Bfh[2]);
                    mma_f16(acc[i][2 * p + 1], Afh[i], &Bfl[2]);
                }
            }
        }
    }

#pragma unroll
    for (int i = 0; i < 2; i++) {
        const int r0 = m0 + wm + i * 16 + g;
#pragma unroll
        for (int j = 0; j < 8; j++) {
            const int cc = n0 + wn + j * 8 + 2 * t;
            float b0 = bias[cc], b1 = bias[cc + 1];
            *(float2*)(C + (long long)r0 * N + cc) =
                make_float2(fmaxf(acc[i][j][0] + b0, 0.f), fmaxf(acc[i][j][1] + b1, 0.f));
            *(float2*)(C + (long long)(r0 + 8) * N + cc) =
                make_float2(fmaxf(acc[i][j][2] + b0, 0.f), fmaxf(acc[i][j][3] + b1, 0.f));
        }
    }
}

// ---------------------------------------------------------------------------
// fused pack: h->h16, Wq/Wk/Wv->fp16, Wo->pair
// ---------------------------------------------------------------------------
#define PK_H (HB_ELEMS / 4)
#define PK_W (W1_ELEMS / 4)
__global__ __launch_bounds__(256) void pack_all(
    const float* __restrict__ h, const float* __restrict__ Wq,
    const float* __restrict__ Wk, const float* __restrict__ Wv,
    const float* __restrict__ Wo,
    __half* __restrict__ h16, __half* __restrict__ wq16,
    __half* __restrict__ wk16, __half* __restrict__ wv16,
    __half* __restrict__ wo2)
{
    const int total = PK_H + 4 * PK_W;
    for (int i = blockIdx.x * blockDim.x + threadIdx.x; i < total;
         i += gridDim.x * blockDim.x) {
        if (i < PK_H + 3 * PK_W) {
            const float* src; __half* dst; int idx;
            if (i < PK_H) { src = h; dst = h16; idx = i; }
            else {
                int r = i - PK_H;
                int seg = r / PK_W; idx = r % PK_W;
                src = (seg == 0) ? Wq : (seg == 1) ? Wk : Wv;
                dst = (seg == 0) ? wq16 : (seg == 1) ? wk16 : wv16;
            }
            float4 v = ((const float4*)src)[idx];
            ((uint2*)dst)[idx] = make_uint2(
                packh2(__float2half_rn(v.x), __float2half_rn(v.y)),
                packh2(__float2half_rn(v.z), __float2half_rn(v.w)));
        } else {
            int idx = i - PK_H - 3 * PK_W;
            float4 v = ((const float4*)Wo)[idx];
            __half h0, l0, h1, l1, h2, l2, h3, l3;
            h_split(v.x, h0, l0); h_split(v.y, h1, l1);
            h_split(v.z, h2, l2); h_split(v.w, h3, l3);
            ((uint2*)wo2)[idx] = make_uint2(packh2(h0, h1), packh2(h2, h3));
            ((uint2*)(wo2 + 2 * W1_ELEMS))[idx] = make_uint2(packh2(l0, l1), packh2(l2, l3));
        }
    }
}

// ---------------------------------------------------------------------------
// kernel_launch — inputs: h, Wv, bv, Wk, bk, Wq, bq, Wo, bo
// ---------------------------------------------------------------------------
extern "C" void kernel_launch(void* const* d_in, const int* in_sizes, int n_in,
                              void* d_out, int out_size)
{
    const float* h  = (const float*)d_in[0];
    const float* Wv = (const float*)d_in[1];
    const float* bv = (const float*)d_in[2];
    const float* Wk = (const float*)d_in[3];
    const float* bk = (const float*)d_in[4];
    const float* Wq = (const float*)d_in[5];
    const float* bq = (const float*)d_in[6];
    const float* Wo = (const float*)d_in[7];
    const float* bo = (const float*)d_in[8];
    float* out = (float*)d_out;

    __half *h16, *wq16, *wk16, *wv16, *wo2, *q, *k, *vt, *e, *o2;
    float *mloc, *rsum;
    cudaGetSymbolAddress((void**)&h16,  g_h16);
    cudaGetSymbolAddress((void**)&wq16, g_wq16);
    cudaGetSymbolAddress((void**)&wk16, g_wk16);
    cudaGetSymbolAddress((void**)&wv16, g_wv16);
    cudaGetSymbolAddress((void**)&wo2,  g_wo2);
    cudaGetSymbolAddress((void**)&q,    g_q);
    cudaGetSymbolAddress((void**)&k,    g_k);
    cudaGetSymbolAddress((void**)&vt,   g_vt);
    cudaGetSymbolAddress((void**)&e,    g_e);
    cudaGetSymbolAddress((void**)&mloc, g_mloc);
    cudaGetSymbolAddress((void**)&rsum, g_rsum);
    cudaGetSymbolAddress((void**)&o2,   g_o2);

    cudaFuncSetAttribute(gemm_proj, cudaFuncAttributeMaxDynamicSharedMemorySize, SSMEM);
    cudaFuncSetAttribute(gemm_qk,   cudaFuncAttributeMaxDynamicSharedMemorySize, SSMEM);
    cudaFuncSetAttribute(gemm_pv,   cudaFuncAttributeMaxDynamicSharedMemorySize, SSMEM);
    cudaFuncSetAttribute(gemm_p3,   cudaFuncAttributeMaxDynamicSharedMemorySize, PSMEM);

    const int M = BB * NN;   // 32768

    // 1. fused pack
    pack_all<<<2048, 256>>>(h, Wq, Wk, Wv, Wo, h16, wq16, wk16, wv16, wo2);

    // 2. fused Q/K/V projections; z==2 writes vt directly
    {
        dim3 grid(HH / BN, M / BM, 3);
        gemm_proj<<<grid, THREADS, SSMEM>>>(h16, wq16, wk16, wv16,
                                            bq, bk, bv, q, k, vt);
    }

    // 3. S GEMM + online exp -> e fp16 + per-tile stats
    {
        dim3 grid(NN / BN, NN / BM, BB);
        gemm_qk<<<grid, THREADS, SSMEM>>>(q, k, e, mloc, rsum);
    }

    // 4. O = scaled-E * Vt^T -> fp16 pair (stats inlined)
    {
        dim3 grid(HH / BN, NN / BM, BB);
        gemm_pv<<<grid, THREADS, SSMEM>>>(e, vt, mloc, rsum, o2, QKV_ELEMS);
    }

    // 5. out = relu(O Wo^T + bo) -> fp32
    {
        dim3 grid(DD / BN, M / BM, 1);
        gemm_p3<<<grid, THREADS, PSMEM>>>(o2, wo2, bo, out, M, DD, HH,
                                          QKV_ELEMS, W1_ELEMS);
    }
}